// round 7
// baseline (speedup 1.0000x reference)
#include <cuda_runtime.h>
#include <cuda_bf16.h>
#include <cstdint>
#include <cstddef>

// ---------------------------------------------------------------------------
// Problem constants
// ---------------------------------------------------------------------------
#define NB   16
#define NH   64
#define NW   64
#define NC   512
#define NIC  64
#define NROWS (NB*NH*NW)          // 65536
#define LN_EPS 1e-3f

// Scratch (device globals = sanctioned no-alloc scratch)
__device__ float d_G[(size_t)NROWS * NIC];
__device__ float d_H[(size_t)NROWS * NIC];
__device__ float d_P[(size_t)NROWS * NIC];

// ---------------------------------------------------------------------------
// packed fp32x2 FMA (FFMA2) — family feature, compiles for sm_103 target
// ---------------------------------------------------------------------------
__device__ __forceinline__ void fma2(unsigned long long& d, unsigned long long a,
                                     unsigned long long b) {
    asm("fma.rn.f32x2 %0, %1, %2, %0;" : "+l"(d) : "l"(a), "l"(b));
}
__device__ __forceinline__ unsigned long long bcast2(float a) {
    unsigned long long r;
    asm("mov.b64 %0, {%1, %1};" : "=l"(r) : "r"(__float_as_uint(a)));
    return r;
}
__device__ __forceinline__ void unpack2(unsigned long long v, float& lo, float& hi) {
    uint32_t a, b;
    asm("mov.b64 {%0, %1}, %2;" : "=r"(a), "=r"(b) : "l"(v));
    lo = __uint_as_float(a); hi = __uint_as_float(b);
}

// ---------------------------------------------------------------------------
// K1: G = LN_f(x @ w_f), H = LN_h(x @ w_h)
// GEMM M=65536, N=128 ([wf | wh]), K=512. Block tile 128x128, BK=16,
// 256 threads, 8x8 register tile as 8x4 packed f32x2 along N.
// LN over each 64-wide half via 8-lane shfl reduction in the epilogue.
// ---------------------------------------------------------------------------
#define K1_BM 128
#define K1_BN 128
#define K1_BK 16

__global__ __launch_bounds__(256)
void k1_gemm_ln(const float* __restrict__ x,
                const float* __restrict__ wf, const float* __restrict__ wh,
                const float* __restrict__ gamma_f, const float* __restrict__ beta_f,
                const float* __restrict__ gamma_h, const float* __restrict__ beta_h)
{
    __shared__ float As[K1_BK][K1_BM];   // x^T tile: As[kk][m]
    __shared__ float Bs[K1_BK][K1_BN];   // [wf | wh]

    const int tid  = threadIdx.x;
    const int row0 = blockIdx.x * K1_BM;
    const int tm   = (tid >> 4) << 3;    // 0..120
    const int tn   = (tid & 15) << 3;    // 0..120

    unsigned long long acc2[8][4];
#pragma unroll
    for (int i = 0; i < 8; i++)
#pragma unroll
        for (int jp = 0; jp < 4; jp++) acc2[i][jp] = 0ULL;

    const int am  = tid >> 1;            // row within A tile (0..127)
    const int ac0 = (tid & 1) * 2;       // float4 chunk base along k

    for (int k0 = 0; k0 < NC; k0 += K1_BK) {
        // ---- load A (x), transposed into smem ----
#pragma unroll
        for (int s = 0; s < 2; s++) {
            const int chunk = ac0 + s;   // 0..3
            const float4 v = *reinterpret_cast<const float4*>(
                x + (size_t)(row0 + am) * NC + k0 + chunk * 4);
            As[chunk * 4 + 0][am] = v.x;
            As[chunk * 4 + 1][am] = v.y;
            As[chunk * 4 + 2][am] = v.z;
            As[chunk * 4 + 3][am] = v.w;
        }
        // ---- load B = [wf | wh] tile 16 x 128 ----
#pragma unroll
        for (int it = 0; it < 2; it++) {
            const int f    = tid + it * 256;     // 0..511 float4 index
            const int kk   = f >> 5;             // 0..15
            const int col4 = (f & 31) * 4;       // 0..124
            const float* src = (col4 < NIC)
                ? (wf + (size_t)(k0 + kk) * NIC + col4)
                : (wh + (size_t)(k0 + kk) * NIC + (col4 - NIC));
            *reinterpret_cast<float4*>(&Bs[kk][col4]) =
                *reinterpret_cast<const float4*>(src);
        }
        __syncthreads();

#pragma unroll
        for (int kk = 0; kk < K1_BK; kk++) {
            float a[8];
            *reinterpret_cast<float4*>(&a[0]) = *reinterpret_cast<const float4*>(&As[kk][tm]);
            *reinterpret_cast<float4*>(&a[4]) = *reinterpret_cast<const float4*>(&As[kk][tm + 4]);
            unsigned long long b2[4];
            const ulonglong2 t0 = *reinterpret_cast<const ulonglong2*>(&Bs[kk][tn]);
            const ulonglong2 t1 = *reinterpret_cast<const ulonglong2*>(&Bs[kk][tn + 4]);
            b2[0] = t0.x; b2[1] = t0.y; b2[2] = t1.x; b2[3] = t1.y;
            unsigned long long a2[8];
#pragma unroll
            for (int i = 0; i < 8; i++) a2[i] = bcast2(a[i]);
#pragma unroll
            for (int i = 0; i < 8; i++)
#pragma unroll
                for (int jp = 0; jp < 4; jp++)
                    fma2(acc2[i][jp], a2[i], b2[jp]);
        }
        __syncthreads();
    }

    // unpack accumulators
    float acc[8][8];
#pragma unroll
    for (int i = 0; i < 8; i++)
#pragma unroll
        for (int jp = 0; jp < 4; jp++)
            unpack2(acc2[i][jp], acc[i][2 * jp], acc[i][2 * jp + 1]);

    // ---- LayerNorm epilogue (per row, per 64-wide half) ----
    const bool isF   = (tn < NIC);
    const int  cbase = tn & (NIC - 1);
    const float* gam = isF ? gamma_f : gamma_h;
    const float* bet = isF ? beta_f  : beta_h;
    float gmv[8], btv[8];
#pragma unroll
    for (int j = 0; j < 8; j++) { gmv[j] = gam[cbase + j]; btv[j] = bet[cbase + j]; }
    float* dstBase = isF ? d_G : d_H;

#pragma unroll
    for (int rr = 0; rr < 8; rr++) {
        float s = 0.0f, ss = 0.0f;
#pragma unroll
        for (int j = 0; j < 8; j++) { const float v = acc[rr][j]; s += v; ss += v * v; }
#pragma unroll
        for (int o = 1; o < 8; o <<= 1) {
            s  += __shfl_xor_sync(0xffffffffu, s,  o);
            ss += __shfl_xor_sync(0xffffffffu, ss, o);
        }
        const float mean = s * (1.0f / NIC);
        const float var  = ss * (1.0f / NIC) - mean * mean;
        const float inv  = rsqrtf(var + LN_EPS);
        float ov[8];
#pragma unroll
        for (int j = 0; j < 8; j++)
            ov[j] = (acc[rr][j] - mean) * inv * gmv[j] + btv[j];
        float* dst = dstBase + (size_t)(row0 + tm + rr) * NIC + cbase;
        *reinterpret_cast<float4*>(dst)     = *reinterpret_cast<float4*>(&ov[0]);
        *reinterpret_cast<float4*>(dst + 4) = *reinterpret_cast<float4*>(&ov[4]);
    }
}

// ---------------------------------------------------------------------------
// K2: P[b,h,w,i] = softmax_h( G[b,w,h,i] * G[b,h,w,i] ) * H[b,h,w,i]
// One block per (b,w). thread = (i = tid%64, h-quarter q = tid/64).
// ---------------------------------------------------------------------------
__global__ __launch_bounds__(256)
void k2_softmax()
{
    __shared__ float red[4][64];
    const int tid = threadIdx.x;
    const int b   = blockIdx.x >> 6;
    const int w   = blockIdx.x & 63;
    const int i   = tid & 63;
    const int q   = tid >> 6;
    const int h0  = q * 16;

    float l[16];
#pragma unroll
    for (int hh = 0; hh < 16; hh++) {
        const int h = h0 + hh;
        const float gw = d_G[((size_t)((b * NH + w) * NW + h)) * NIC + i]; // g[b,w,h,i]
        const float gc = d_G[((size_t)((b * NH + h) * NW + w)) * NIC + i]; // g[b,h,w,i]
        l[hh] = gw * gc;
    }
    float m = l[0];
#pragma unroll
    for (int hh = 1; hh < 16; hh++) m = fmaxf(m, l[hh]);
    red[q][i] = m;
    __syncthreads();
    const float M = fmaxf(fmaxf(red[0][i], red[1][i]), fmaxf(red[2][i], red[3][i]));
    __syncthreads();

    float s = 0.0f;
#pragma unroll
    for (int hh = 0; hh < 16; hh++) {
        const float e = __expf(l[hh] - M);
        l[hh] = e;
        s += e;
    }
    red[q][i] = s;
    __syncthreads();
    const float S    = red[0][i] + red[1][i] + red[2][i] + red[3][i];
    const float rinv = 1.0f / S;

#pragma unroll
    for (int hh = 0; hh < 16; hh++) {
        const int h = h0 + hh;
        const size_t o = ((size_t)((b * NH + h) * NW + w)) * NIC + i;
        d_P[o] = l[hh] * rinv * d_H[o];
    }
}

// ---------------------------------------------------------------------------
// K3: out = x + LN_fgh(P @ w_fgh) * scale   — packed fma.rn.f32x2.
// Block tile 32x512, BK=16, 256 threads, 8x8 register tile (as 8x4 f32x2).
// ---------------------------------------------------------------------------
#define K3_BM 32
#define K3_BK 16

__global__ __launch_bounds__(256)
void k3_gemm_ln_res(const float* __restrict__ wfgh,
                    const float* __restrict__ gamma, const float* __restrict__ beta,
                    const float* __restrict__ scale,
                    const float* __restrict__ x,
                    float* __restrict__ out)
{
    __shared__ float As[K3_BK][K3_BM];       // P^T tile
    __shared__ float Bs[K3_BK][NC];          // 32 KB
    __shared__ float red2[4][8][2][2];       // [group][rr][warp-parity][{sum,sumsq}]

    const int tid  = threadIdx.x;
    const int row0 = blockIdx.x * K3_BM;
    const int g    = tid >> 6;               // row group 0..3
    const int tm   = g << 3;                 // 0,8,16,24
    const int tn   = (tid & 63) << 3;        // 0..504
    const int wp   = (tid >> 5) & 1;         // warp parity within group
    const int lane = tid & 31;

    unsigned long long acc2[8][4];
#pragma unroll
    for (int i = 0; i < 8; i++)
#pragma unroll
        for (int jp = 0; jp < 4; jp++) acc2[i][jp] = 0ULL;

    for (int k0 = 0; k0 < NIC; k0 += K3_BK) {
        if (tid < 128) {                     // A: 32x16 = 128 float4
            const int m     = tid >> 2;
            const int chunk = tid & 3;
            const float4 v = *reinterpret_cast<const float4*>(
                d_P + (size_t)(row0 + m) * NIC + k0 + chunk * 4);
            As[chunk * 4 + 0][m] = v.x;
            As[chunk * 4 + 1][m] = v.y;
            As[chunk * 4 + 2][m] = v.z;
            As[chunk * 4 + 3][m] = v.w;
        }
#pragma unroll
        for (int it = 0; it < 8; it++) {     // B: 16x512 = 2048 float4
            const int f  = tid + it * 256;
            const int kk = f >> 7;           // 0..15
            const int c4 = (f & 127) * 4;    // 0..508
            *reinterpret_cast<float4*>(&Bs[kk][c4]) =
                *reinterpret_cast<const float4*>(wfgh + (size_t)(k0 + kk) * NC + c4);
        }
        __syncthreads();

#pragma unroll
        for (int kk = 0; kk < K3_BK; kk++) {
            float a[8];
            *reinterpret_cast<float4*>(&a[0]) = *reinterpret_cast<const float4*>(&As[kk][tm]);
            *reinterpret_cast<float4*>(&a[4]) = *reinterpret_cast<const float4*>(&As[kk][tm + 4]);
            unsigned long long b2[4];
            const ulonglong2 t0 = *reinterpret_cast<const ulonglong2*>(&Bs[kk][tn]);
            const ulonglong2 t1 = *reinterpret_cast<const ulonglong2*>(&Bs[kk][tn + 4]);
            b2[0] = t0.x; b2[1] = t0.y; b2[2] = t1.x; b2[3] = t1.y;
            unsigned long long a2[8];
#pragma unroll
            for (int i = 0; i < 8; i++) a2[i] = bcast2(a[i]);
#pragma unroll
            for (int i = 0; i < 8; i++)
#pragma unroll
                for (int jp = 0; jp < 4; jp++)
                    fma2(acc2[i][jp], a2[i], b2[jp]);
        }
        __syncthreads();
    }

    // unpack
    float acc[8][8];
#pragma unroll
    for (int i = 0; i < 8; i++)
#pragma unroll
        for (int jp = 0; jp < 4; jp++)
            unpack2(acc2[i][jp], acc[i][2 * jp], acc[i][2 * jp + 1]);

    // per-row LN reduction: warp shfl then 2-warp smem combine
#pragma unroll
    for (int rr = 0; rr < 8; rr++) {
        float s = 0.0f, ss = 0.0f;
#pragma unroll
        for (int j = 0; j < 8; j++) { const float v = acc[rr][j]; s += v; ss += v * v; }
#pragma unroll
        for (int o = 1; o < 32; o <<= 1) {
            s  += __shfl_xor_sync(0xffffffffu, s,  o);
            ss += __shfl_xor_sync(0xffffffffu, ss, o);
        }
        if (lane == 0) { red2[g][rr][wp][0] = s; red2[g][rr][wp][1] = ss; }
    }
    __syncthreads();

    const float sc = scale[0];
    float gmv[8], btv[8];
#pragma unroll
    for (int j = 0; j < 8; j++) { gmv[j] = gamma[tn + j]; btv[j] = beta[tn + j]; }

#pragma unroll
    for (int rr = 0; rr < 8; rr++) {
        const float S    = red2[g][rr][0][0] + red2[g][rr][1][0];
        const float SS   = red2[g][rr][0][1] + red2[g][rr][1][1];
        const float mean = S * (1.0f / NC);
        const float var  = SS * (1.0f / NC) - mean * mean;
        const float inv  = rsqrtf(var + LN_EPS);
        const size_t r   = (size_t)(row0 + tm + rr);

        float xv[8];
        *reinterpret_cast<float4*>(&xv[0]) = *reinterpret_cast<const float4*>(x + r * NC + tn);
        *reinterpret_cast<float4*>(&xv[4]) = *reinterpret_cast<const float4*>(x + r * NC + tn + 4);

        float ov[8];
#pragma unroll
        for (int j = 0; j < 8; j++)
            ov[j] = xv[j] + ((acc[rr][j] - mean) * inv * gmv[j] + btv[j]) * sc;

        float* dst = out + r * NC + tn;
        *reinterpret_cast<float4*>(dst)     = *reinterpret_cast<float4*>(&ov[0]);
        *reinterpret_cast<float4*>(dst + 4) = *reinterpret_cast<float4*>(&ov[4]);
    }
}

// ---------------------------------------------------------------------------
// Launch. Inputs: 0:x 1:w_f 2:w_h 3:w_fgh 4:gamma_f 5:beta_f 6:gamma_h
// 7:beta_h 8:gamma_fgh 9:beta_fgh 10:scale
// ---------------------------------------------------------------------------
extern "C" void kernel_launch(void* const* d_in, const int* in_sizes, int n_in,
                              void* d_out, int out_size)
{
    (void)in_sizes; (void)n_in; (void)out_size;
    const float* x         = (const float*)d_in[0];
    const float* w_f       = (const float*)d_in[1];
    const float* w_h       = (const float*)d_in[2];
    const float* w_fgh     = (const float*)d_in[3];
    const float* gamma_f   = (const float*)d_in[4];
    const float* beta_f    = (const float*)d_in[5];
    const float* gamma_h   = (const float*)d_in[6];
    const float* beta_h    = (const float*)d_in[7];
    const float* gamma_fgh = (const float*)d_in[8];
    const float* beta_fgh  = (const float*)d_in[9];
    const float* scale     = (const float*)d_in[10];
    float* out             = (float*)d_out;

    k1_gemm_ln<<<NROWS / K1_BM, 256>>>(x, w_f, w_h,
                                       gamma_f, beta_f, gamma_h, beta_h);
    k2_softmax<<<NB * NW, 256>>>();
    k3_gemm_ln_res<<<NROWS / K3_BM, 256>>>(w_fgh, gamma_fgh, beta_fgh,
                                           scale, x, out);
}

// round 8
// speedup vs baseline: 1.1949x; 1.1949x over previous
#include <cuda_runtime.h>
#include <cuda_bf16.h>
#include <cstdint>
#include <cstddef>

// ---------------------------------------------------------------------------
// Problem constants
// ---------------------------------------------------------------------------
#define NB   16
#define NH   64
#define NW   64
#define NC   512
#define NIC  64
#define NROWS (NB*NH*NW)          // 65536
#define LN_EPS 1e-3f

// Scratch (device globals = sanctioned no-alloc scratch)
__device__ float d_G [(size_t)NROWS * NIC];
__device__ float d_Hs[(size_t)NROWS * NIC];
__device__ __nv_bfloat16 d_Phi[(size_t)NROWS * NIC];
__device__ __nv_bfloat16 d_Plo[(size_t)NROWS * NIC];
// Pre-split weights: [wf|wh] as [512][128], w_fgh as [64][512]
__device__ __nv_bfloat16 d_WH[512 * 128];
__device__ __nv_bfloat16 d_WL[512 * 128];
__device__ __nv_bfloat16 d_FH[64 * 512];
__device__ __nv_bfloat16 d_FL[64 * 512];

// ---------------------------------------------------------------------------
// Helpers: family-feature tensor path (sm_80 mma.sync + ldmatrix)
// ---------------------------------------------------------------------------
__device__ __forceinline__ uint32_t smem_u32(const void* p) {
    uint32_t a;
    asm("{ .reg .u64 t; cvta.to.shared.u64 t, %1; cvt.u32.u64 %0, t; }"
        : "=r"(a) : "l"(p));
    return a;
}
__device__ __forceinline__ void ldsm4(uint32_t r[4], uint32_t a) {
    asm volatile("ldmatrix.sync.aligned.m8n8.x4.shared.b16 {%0,%1,%2,%3}, [%4];"
                 : "=r"(r[0]), "=r"(r[1]), "=r"(r[2]), "=r"(r[3]) : "r"(a));
}
__device__ __forceinline__ void ldsm4t(uint32_t r[4], uint32_t a) {
    asm volatile("ldmatrix.sync.aligned.m8n8.x4.trans.shared.b16 {%0,%1,%2,%3}, [%4];"
                 : "=r"(r[0]), "=r"(r[1]), "=r"(r[2]), "=r"(r[3]) : "r"(a));
}
__device__ __forceinline__ void mma16816(float c[4], const uint32_t a[4],
                                         uint32_t b0, uint32_t b1) {
    asm volatile(
        "mma.sync.aligned.m16n8k16.row.col.f32.bf16.bf16.f32 "
        "{%0,%1,%2,%3}, {%4,%5,%6,%7}, {%8,%9}, {%0,%1,%2,%3};"
        : "+f"(c[0]), "+f"(c[1]), "+f"(c[2]), "+f"(c[3])
        : "r"(a[0]), "r"(a[1]), "r"(a[2]), "r"(a[3]), "r"(b0), "r"(b1));
}
__device__ __forceinline__ void hilo(float v, __nv_bfloat16& h, __nv_bfloat16& l) {
    h = __float2bfloat16(v);
    l = __float2bfloat16(v - __bfloat162float(h));
}

// ---------------------------------------------------------------------------
// K0: pre-split weights to bf16 hi/lo. [wf|wh] -> d_WH/WL [512][128];
// w_fgh -> d_FH/FL [64][512]. Grid covers 65536 + 32768 exactly.
// ---------------------------------------------------------------------------
__global__ __launch_bounds__(256)
void k0_prep(const float* __restrict__ wf, const float* __restrict__ wh,
             const float* __restrict__ wfgh)
{
    const int id = blockIdx.x * 256 + threadIdx.x;
    if (id < 512 * 128) {
        const int k = id >> 7, n = id & 127;
        const float v = (n < NIC) ? wf[k * NIC + n] : wh[k * NIC + (n - NIC)];
        __nv_bfloat16 h, l; hilo(v, h, l);
        d_WH[id] = h; d_WL[id] = l;
    } else {
        const int id2 = id - 512 * 128;
        __nv_bfloat16 h, l; hilo(wfgh[id2], h, l);
        d_FH[id2] = h; d_FL[id2] = l;
    }
}

// ---------------------------------------------------------------------------
// K1: G = LN_f(x @ wf), H = LN_h(x @ wh) via bf16 mma.sync 3-product split.
// CTA 128(M) x 128(N), K-chunk 32, 16 chunks, 8 warps (warp tile 64x32).
// smem (dynamic, 66 KB): A_hi[128][40] A_lo | B_hi[32][136] B_lo ; reused as
// C[128][132] fp32 for the LN staging pass.
// ---------------------------------------------------------------------------
#define K1_SMEM 67584
#define A_STR 40      // bf16 elems; 80B rows -> ldmatrix bank-disjoint
#define B1_STR 136    // 272B rows -> bank-disjoint

__global__ __launch_bounds__(256, 1)
void k1_mma(const float* __restrict__ x,
            const float* __restrict__ gamma_f, const float* __restrict__ beta_f,
            const float* __restrict__ gamma_h, const float* __restrict__ beta_h)
{
    extern __shared__ char sm[];
    const uint32_t su = smem_u32(sm);
    const int AH = 0, AL = 10240, BH = 20480, BL = 29184;

    const int tid  = threadIdx.x;
    const int wid  = tid >> 5;
    const int lane = tid & 31;
    const int wm   = wid & 1;        // warp row block (64 rows)
    const int wn   = wid >> 1;       // warp col block (32 cols)
    const int row0 = blockIdx.x * 128;

    float acc[4][4][4];
#pragma unroll
    for (int mi = 0; mi < 4; mi++)
#pragma unroll
        for (int ni = 0; ni < 4; ni++)
#pragma unroll
            for (int q = 0; q < 4; q++) acc[mi][ni][q] = 0.0f;

    // prefetch registers
    float4 pa[4];
    uint2  pbh[4], pbl[4];

    // chunk c: A = x[row0.., c*32..], B = d_WH/WL rows c*32..
#define K1_LOAD(c) do {                                                         \
    _Pragma("unroll")                                                           \
    for (int it = 0; it < 4; it++) {                                            \
        const int f4 = tid + it * 256;                                          \
        const int m  = f4 >> 3, kc = (f4 & 7) * 4;                              \
        pa[it] = *reinterpret_cast<const float4*>(                              \
            x + (size_t)(row0 + m) * NC + (c) * 32 + kc);                       \
        const int k = f4 >> 5, nc = (f4 & 31) * 4;                              \
        pbh[it] = *reinterpret_cast<const uint2*>(d_WH + ((c) * 32 + k) * 128 + nc); \
        pbl[it] = *reinterpret_cast<const uint2*>(d_WL + ((c) * 32 + k) * 128 + nc); \
    } } while (0)

    K1_LOAD(0);

    for (int c = 0; c < 16; c++) {
        // ---- store prefetched chunk to smem (convert A to hi/lo) ----
#pragma unroll
        for (int it = 0; it < 4; it++) {
            const int f4 = tid + it * 256;
            const int m  = f4 >> 3, kc = (f4 & 7) * 4;
            union { __nv_bfloat16 e[4]; uint2 u; } hh, ll;
            hilo(pa[it].x, hh.e[0], ll.e[0]);
            hilo(pa[it].y, hh.e[1], ll.e[1]);
            hilo(pa[it].z, hh.e[2], ll.e[2]);
            hilo(pa[it].w, hh.e[3], ll.e[3]);
            *reinterpret_cast<uint2*>(sm + AH + m * (A_STR * 2) + kc * 2) = hh.u;
            *reinterpret_cast<uint2*>(sm + AL + m * (A_STR * 2) + kc * 2) = ll.u;
            const int k = f4 >> 5, nc = (f4 & 31) * 4;
            *reinterpret_cast<uint2*>(sm + BH + k * (B1_STR * 2) + nc * 2) = pbh[it];
            *reinterpret_cast<uint2*>(sm + BL + k * (B1_STR * 2) + nc * 2) = pbl[it];
        }
        __syncthreads();

        if (c < 15) K1_LOAD(c + 1);

        // ---- tensor math on current chunk ----
#pragma unroll
        for (int ks = 0; ks < 32; ks += 16) {
            uint32_t ah[4][4], al_[4][4];
#pragma unroll
            for (int mi = 0; mi < 4; mi++) {
                const uint32_t off =
                    ((wm * 64 + mi * 16 + (lane & 15)) * A_STR + ks + (lane >> 4) * 8) * 2;
                ldsm4(ah[mi],  su + AH + off);
                ldsm4(al_[mi], su + AL + off);
            }
            uint32_t bh[2][4], bl[2][4];
#pragma unroll
            for (int p = 0; p < 2; p++) {
                const uint32_t off =
                    ((ks + (lane & 15)) * B1_STR + wn * 32 + p * 16 + (lane >> 4) * 8) * 2;
                ldsm4t(bh[p], su + BH + off);
                ldsm4t(bl[p], su + BL + off);
            }
#pragma unroll
            for (int mi = 0; mi < 4; mi++)
#pragma unroll
                for (int p = 0; p < 2; p++)
#pragma unroll
                    for (int ns = 0; ns < 2; ns++) {
                        const int ni = p * 2 + ns;
                        mma16816(acc[mi][ni], ah[mi],  bh[p][2 * ns], bh[p][2 * ns + 1]);
                        mma16816(acc[mi][ni], ah[mi],  bl[p][2 * ns], bl[p][2 * ns + 1]);
                        mma16816(acc[mi][ni], al_[mi], bh[p][2 * ns], bh[p][2 * ns + 1]);
                    }
        }
        __syncthreads();
    }

    // ---- stage C in smem: [128][132] fp32 ----
    float* Csm = reinterpret_cast<float*>(sm);
#pragma unroll
    for (int mi = 0; mi < 4; mi++)
#pragma unroll
        for (int ni = 0; ni < 4; ni++) {
            const int row = wm * 64 + mi * 16 + (lane >> 2);
            const int col = wn * 32 + ni * 8 + (lane & 3) * 2;
            *reinterpret_cast<float2*>(&Csm[row * 132 + col]) =
                make_float2(acc[mi][ni][0], acc[mi][ni][1]);
            *reinterpret_cast<float2*>(&Csm[(row + 8) * 132 + col]) =
                make_float2(acc[mi][ni][2], acc[mi][ni][3]);
        }
    __syncthreads();

    // ---- LN: one thread per (row, 64-half) ----
    {
        const int row  = tid >> 1;
        const int half = tid & 1;
        const float* base = &Csm[row * 132 + half * 64];
        float4 v[16];
        float s = 0.f, ss = 0.f;
#pragma unroll
        for (int j = 0; j < 16; j++) {
            v[j] = *reinterpret_cast<const float4*>(base + j * 4);
            s  += v[j].x + v[j].y + v[j].z + v[j].w;
            ss += v[j].x * v[j].x + v[j].y * v[j].y + v[j].z * v[j].z + v[j].w * v[j].w;
        }
        const float mean = s * (1.0f / NIC);
        const float var  = ss * (1.0f / NIC) - mean * mean;
        const float inv  = rsqrtf(var + LN_EPS);
        const float* gam = half ? gamma_h : gamma_f;
        const float* bet = half ? beta_h  : beta_f;
        float* dst = (half ? d_Hs : d_G) + (size_t)(row0 + row) * NIC;
#pragma unroll
        for (int j = 0; j < 16; j++) {
            const float4 g4 = *reinterpret_cast<const float4*>(gam + j * 4);
            const float4 b4 = *reinterpret_cast<const float4*>(bet + j * 4);
            float4 o;
            o.x = (v[j].x - mean) * inv * g4.x + b4.x;
            o.y = (v[j].y - mean) * inv * g4.y + b4.y;
            o.z = (v[j].z - mean) * inv * g4.z + b4.z;
            o.w = (v[j].w - mean) * inv * g4.w + b4.w;
            *reinterpret_cast<float4*>(dst + j * 4) = o;
        }
    }
#undef K1_LOAD
}

// ---------------------------------------------------------------------------
// K2: P = softmax_h( G[b,w,h,i] * G[b,h,w,i] ) * H  -> bf16 hi/lo planes
// ---------------------------------------------------------------------------
__global__ __launch_bounds__(256)
void k2_softmax()
{
    __shared__ float red[4][64];
    const int tid = threadIdx.x;
    const int b   = blockIdx.x >> 6;
    const int w   = blockIdx.x & 63;
    const int i   = tid & 63;
    const int q   = tid >> 6;
    const int h0  = q * 16;

    float l[16];
#pragma unroll
    for (int hh = 0; hh < 16; hh++) {
        const int h = h0 + hh;
        const float gw = d_G[((size_t)((b * NH + w) * NW + h)) * NIC + i];
        const float gc = d_G[((size_t)((b * NH + h) * NW + w)) * NIC + i];
        l[hh] = gw * gc;
    }
    float m = l[0];
#pragma unroll
    for (int hh = 1; hh < 16; hh++) m = fmaxf(m, l[hh]);
    red[q][i] = m;
    __syncthreads();
    const float M = fmaxf(fmaxf(red[0][i], red[1][i]), fmaxf(red[2][i], red[3][i]));
    __syncthreads();

    float s = 0.0f;
#pragma unroll
    for (int hh = 0; hh < 16; hh++) {
        const float e = __expf(l[hh] - M);
        l[hh] = e;
        s += e;
    }
    red[q][i] = s;
    __syncthreads();
    const float S    = red[0][i] + red[1][i] + red[2][i] + red[3][i];
    const float rinv = 1.0f / S;

#pragma unroll
    for (int hh = 0; hh < 16; hh++) {
        const int h = h0 + hh;
        const size_t o = ((size_t)((b * NH + h) * NW + w)) * NIC + i;
        const float v = l[hh] * rinv * d_Hs[o];
        __nv_bfloat16 ph, pl; hilo(v, ph, pl);
        d_Phi[o] = ph;
        d_Plo[o] = pl;
    }
}

// ---------------------------------------------------------------------------
// K3: out = x + LN_fgh(P @ w_fgh) * scale, bf16 mma 3-product split.
// CTA 32(M) x 512(N), K=64 in 2 chunks of 32. 8 warps, warp tile 32x64.
// smem: A_hi[32][40] A_lo | B_hi[32][520] B_lo (70 KB); reused as C[32][516].
// ---------------------------------------------------------------------------
#define K3_SMEM 71680
#define B3_STR 520

__global__ __launch_bounds__(256, 1)
void k3_mma(const float* __restrict__ gamma, const float* __restrict__ beta,
            const float* __restrict__ scale,
            const float* __restrict__ x, float* __restrict__ out)
{
    extern __shared__ char sm[];
    const uint32_t su = smem_u32(sm);
    const int AH = 0, AL = 2560, BH = 5120, BL = 38400;

    const int tid  = threadIdx.x;
    const int wid  = tid >> 5;       // warp n-block (64 cols)
    const int lane = tid & 31;
    const int row0 = blockIdx.x * 32;

    float acc[2][8][4];
#pragma unroll
    for (int mi = 0; mi < 2; mi++)
#pragma unroll
        for (int ni = 0; ni < 8; ni++)
#pragma unroll
            for (int q = 0; q < 4; q++) acc[mi][ni][q] = 0.0f;

    for (int c = 0; c < 2; c++) {
        // A: P hi/lo, 32x32 bf16 per plane (1 uint2/thread/plane)
        {
            const int m = tid >> 3, kc = (tid & 7) * 4;
            const size_t goff = (size_t)(row0 + m) * NIC + c * 32 + kc;
            *reinterpret_cast<uint2*>(sm + AH + m * (A_STR * 2) + kc * 2) =
                *reinterpret_cast<const uint2*>(d_Phi + goff);
            *reinterpret_cast<uint2*>(sm + AL + m * (A_STR * 2) + kc * 2) =
                *reinterpret_cast<const uint2*>(d_Plo + goff);
        }
        // B: w_fgh hi/lo, 32x512 bf16 per plane
#pragma unroll
        for (int it = 0; it < 16; it++) {
            const int f4 = tid + it * 256;
            const int k = f4 >> 7, nc = (f4 & 127) * 4;
            *reinterpret_cast<uint2*>(sm + BH + k * (B3_STR * 2) + nc * 2) =
                *reinterpret_cast<const uint2*>(d_FH + (c * 32 + k) * NC + nc);
            *reinterpret_cast<uint2*>(sm + BL + k * (B3_STR * 2) + nc * 2) =
                *reinterpret_cast<const uint2*>(d_FL + (c * 32 + k) * NC + nc);
        }
        __syncthreads();

#pragma unroll
        for (int ks = 0; ks < 32; ks += 16) {
            uint32_t ah[2][4], al_[2][4];
#pragma unroll
            for (int mi = 0; mi < 2; mi++) {
                const uint32_t off =
                    ((mi * 16 + (lane & 15)) * A_STR + ks + (lane >> 4) * 8) * 2;
                ldsm4(ah[mi],  su + AH + off);
                ldsm4(al_[mi], su + AL + off);
            }
            uint32_t bh[4][4], bl[4][4];
#pragma unroll
            for (int p = 0; p < 4; p++) {
                const uint32_t off =
                    ((ks + (lane & 15)) * B3_STR + wid * 64 + p * 16 + (lane >> 4) * 8) * 2;
                ldsm4t(bh[p], su + BH + off);
                ldsm4t(bl[p], su + BL + off);
            }
#pragma unroll
            for (int mi = 0; mi < 2; mi++)
#pragma unroll
                for (int p = 0; p < 4; p++)
#pragma unroll
                    for (int ns = 0; ns < 2; ns++) {
                        const int ni = p * 2 + ns;
                        mma16816(acc[mi][ni], ah[mi],  bh[p][2 * ns], bh[p][2 * ns + 1]);
                        mma16816(acc[mi][ni], ah[mi],  bl[p][2 * ns], bl[p][2 * ns + 1]);
                        mma16816(acc[mi][ni], al_[mi], bh[p][2 * ns], bh[p][2 * ns + 1]);
                    }
        }
        __syncthreads();
    }

    // ---- stage C [32][516] ----
    float* Csm = reinterpret_cast<float*>(sm);
#pragma unroll
    for (int mi = 0; mi < 2; mi++)
#pragma unroll
        for (int ni = 0; ni < 8; ni++) {
            const int row = mi * 16 + (lane >> 2);
            const int col = wid * 64 + ni * 8 + (lane & 3) * 2;
            *reinterpret_cast<float2*>(&Csm[row * 516 + col]) =
                make_float2(acc[mi][ni][0], acc[mi][ni][1]);
            *reinterpret_cast<float2*>(&Csm[(row + 8) * 516 + col]) =
                make_float2(acc[mi][ni][2], acc[mi][ni][3]);
        }
    __syncthreads();

    // ---- LN + residual: 8 threads per row (consecutive lanes) ----
    {
        const int row = tid >> 3;
        const int cc  = tid & 7;
        const float* base = &Csm[row * 516 + cc * 64];
        float s = 0.f, ss = 0.f;
        float4 v[16];
#pragma unroll
        for (int j = 0; j < 16; j++) {
            v[j] = *reinterpret_cast<const float4*>(base + j * 4);
            s  += v[j].x + v[j].y + v[j].z + v[j].w;
            ss += v[j].x * v[j].x + v[j].y * v[j].y + v[j].z * v[j].z + v[j].w * v[j].w;
        }
#pragma unroll
        for (int o = 1; o < 8; o <<= 1) {
            s  += __shfl_xor_sync(0xffffffffu, s,  o);
            ss += __shfl_xor_sync(0xffffffffu, ss, o);
        }
        const float mean = s * (1.0f / NC);
        const float var  = ss * (1.0f / NC) - mean * mean;
        const float inv  = rsqrtf(var + LN_EPS);
        const float sc   = scale[0];
        const size_t r   = (size_t)(row0 + row);
        const float* xr  = x + r * NC + cc * 64;
        float* dst       = out + r * NC + cc * 64;
        const float* gam = gamma + cc * 64;
        const float* bet = beta  + cc * 64;
#pragma unroll
        for (int j = 0; j < 16; j++) {
            const float4 x4 = *reinterpret_cast<const float4*>(xr + j * 4);
            const float4 g4 = *reinterpret_cast<const float4*>(gam + j * 4);
            const float4 b4 = *reinterpret_cast<const float4*>(bet + j * 4);
            float4 o;
            o.x = x4.x + ((v[j].x - mean) * inv * g4.x + b4.x) * sc;
            o.y = x4.y + ((v[j].y - mean) * inv * g4.y + b4.y) * sc;
            o.z = x4.z + ((v[j].z - mean) * inv * g4.z + b4.z) * sc;
            o.w = x4.w + ((v[j].w - mean) * inv * g4.w + b4.w) * sc;
            *reinterpret_cast<float4*>(dst + j * 4) = o;
        }
    }
}

// ---------------------------------------------------------------------------
// Launch. Inputs: 0:x 1:w_f 2:w_h 3:w_fgh 4:gamma_f 5:beta_f 6:gamma_h
// 7:beta_h 8:gamma_fgh 9:beta_fgh 10:scale
// ---------------------------------------------------------------------------
extern "C" void kernel_launch(void* const* d_in, const int* in_sizes, int n_in,
                              void* d_out, int out_size)
{
    (void)in_sizes; (void)n_in; (void)out_size;
    const float* x         = (const float*)d_in[0];
    const float* w_f       = (const float*)d_in[1];
    const float* w_h       = (const float*)d_in[2];
    const float* w_fgh     = (const float*)d_in[3];
    const float* gamma_f   = (const float*)d_in[4];
    const float* beta_f    = (const float*)d_in[5];
    const float* gamma_h   = (const float*)d_in[6];
    const float* beta_h    = (const float*)d_in[7];
    const float* gamma_fgh = (const float*)d_in[8];
    const float* beta_fgh  = (const float*)d_in[9];
    const float* scale     = (const float*)d_in[10];
    float* out             = (float*)d_out;

    cudaFuncSetAttribute(k1_mma, cudaFuncAttributeMaxDynamicSharedMemorySize, K1_SMEM);
    cudaFuncSetAttribute(k3_mma, cudaFuncAttributeMaxDynamicSharedMemorySize, K3_SMEM);

    k0_prep<<<384, 256>>>(w_f, w_h, w_fgh);
    k1_mma<<<NROWS / 128, 256, K1_SMEM>>>(x, gamma_f, beta_f, gamma_h, beta_h);
    k2_softmax<<<NB * NW, 256>>>();
    k3_mma<<<NROWS / 32, 256, K3_SMEM>>>(gamma_fgh, beta_fgh, scale, x, out);
}

// round 9
// speedup vs baseline: 1.7226x; 1.4416x over previous
#include <cuda_runtime.h>
#include <cuda_bf16.h>
#include <cstdint>
#include <cstddef>

// ---------------------------------------------------------------------------
// Problem constants
// ---------------------------------------------------------------------------
#define NB   16
#define NH   64
#define NW   64
#define NC   512
#define NIC  64
#define NROWS (NB*NH*NW)          // 65536
#define LN_EPS 1e-3f

// Scratch (device globals = sanctioned no-alloc scratch)
__device__ float d_G [(size_t)NROWS * NIC];
__device__ float d_Hs[(size_t)NROWS * NIC];
__device__ __nv_bfloat16 d_Phi[(size_t)NROWS * NIC];
__device__ __nv_bfloat16 d_Plo[(size_t)NROWS * NIC];
// Pre-split weights: [wf|wh] as [512][128], w_fgh as [64][512]
__device__ __nv_bfloat16 d_WH[512 * 128];
__device__ __nv_bfloat16 d_WL[512 * 128];
__device__ __nv_bfloat16 d_FH[64 * 512];
__device__ __nv_bfloat16 d_FL[64 * 512];

// ---------------------------------------------------------------------------
// Helpers: family-feature tensor path (sm_80 mma.sync + ldmatrix)
// ---------------------------------------------------------------------------
__device__ __forceinline__ uint32_t smem_u32(const void* p) {
    uint32_t a;
    asm("{ .reg .u64 t; cvta.to.shared.u64 t, %1; cvt.u32.u64 %0, t; }"
        : "=r"(a) : "l"(p));
    return a;
}
__device__ __forceinline__ void ldsm4(uint32_t r[4], uint32_t a) {
    asm volatile("ldmatrix.sync.aligned.m8n8.x4.shared.b16 {%0,%1,%2,%3}, [%4];"
                 : "=r"(r[0]), "=r"(r[1]), "=r"(r[2]), "=r"(r[3]) : "r"(a));
}
__device__ __forceinline__ void ldsm4t(uint32_t r[4], uint32_t a) {
    asm volatile("ldmatrix.sync.aligned.m8n8.x4.trans.shared.b16 {%0,%1,%2,%3}, [%4];"
                 : "=r"(r[0]), "=r"(r[1]), "=r"(r[2]), "=r"(r[3]) : "r"(a));
}
__device__ __forceinline__ void mma16816(float c[4], const uint32_t a[4],
                                         uint32_t b0, uint32_t b1) {
    asm volatile(
        "mma.sync.aligned.m16n8k16.row.col.f32.bf16.bf16.f32 "
        "{%0,%1,%2,%3}, {%4,%5,%6,%7}, {%8,%9}, {%0,%1,%2,%3};"
        : "+f"(c[0]), "+f"(c[1]), "+f"(c[2]), "+f"(c[3])
        : "r"(a[0]), "r"(a[1]), "r"(a[2]), "r"(a[3]), "r"(b0), "r"(b1));
}
__device__ __forceinline__ void hilo(float v, __nv_bfloat16& h, __nv_bfloat16& l) {
    h = __float2bfloat16(v);
    l = __float2bfloat16(v - __bfloat162float(h));
}

// ---------------------------------------------------------------------------
// K0: pre-split weights to bf16 hi/lo.
// ---------------------------------------------------------------------------
__global__ __launch_bounds__(256)
void k0_prep(const float* __restrict__ wf, const float* __restrict__ wh,
             const float* __restrict__ wfgh)
{
    const int id = blockIdx.x * 256 + threadIdx.x;
    if (id < 512 * 128) {
        const int k = id >> 7, n = id & 127;
        const float v = (n < NIC) ? wf[k * NIC + n] : wh[k * NIC + (n - NIC)];
        __nv_bfloat16 h, l; hilo(v, h, l);
        d_WH[id] = h; d_WL[id] = l;
    } else {
        const int id2 = id - 512 * 128;
        __nv_bfloat16 h, l; hilo(wfgh[id2], h, l);
        d_FH[id2] = h; d_FL[id2] = l;
    }
}

// ---------------------------------------------------------------------------
// K1: G = LN_f(x @ wf), H = LN_h(x @ wh) via bf16 mma.sync 3-product split.
// (unchanged from R8 — passed at ~113us)
// ---------------------------------------------------------------------------
#define K1_SMEM 67584
#define A_STR 40
#define B1_STR 136

__global__ __launch_bounds__(256, 1)
void k1_mma(const float* __restrict__ x,
            const float* __restrict__ gamma_f, const float* __restrict__ beta_f,
            const float* __restrict__ gamma_h, const float* __restrict__ beta_h)
{
    extern __shared__ char sm[];
    const uint32_t su = smem_u32(sm);
    const int AH = 0, AL = 10240, BH = 20480, BL = 29184;

    const int tid  = threadIdx.x;
    const int wid  = tid >> 5;
    const int lane = tid & 31;
    const int wm   = wid & 1;
    const int wn   = wid >> 1;
    const int row0 = blockIdx.x * 128;

    float acc[4][4][4];
#pragma unroll
    for (int mi = 0; mi < 4; mi++)
#pragma unroll
        for (int ni = 0; ni < 4; ni++)
#pragma unroll
            for (int q = 0; q < 4; q++) acc[mi][ni][q] = 0.0f;

    float4 pa[4];
    uint2  pbh[4], pbl[4];

#define K1_LOAD(c) do {                                                         \
    _Pragma("unroll")                                                           \
    for (int it = 0; it < 4; it++) {                                            \
        const int f4 = tid + it * 256;                                          \
        const int m  = f4 >> 3, kc = (f4 & 7) * 4;                              \
        pa[it] = *reinterpret_cast<const float4*>(                              \
            x + (size_t)(row0 + m) * NC + (c) * 32 + kc);                       \
        const int k = f4 >> 5, nc = (f4 & 31) * 4;                              \
        pbh[it] = *reinterpret_cast<const uint2*>(d_WH + ((c) * 32 + k) * 128 + nc); \
        pbl[it] = *reinterpret_cast<const uint2*>(d_WL + ((c) * 32 + k) * 128 + nc); \
    } } while (0)

    K1_LOAD(0);

    for (int c = 0; c < 16; c++) {
#pragma unroll
        for (int it = 0; it < 4; it++) {
            const int f4 = tid + it * 256;
            const int m  = f4 >> 3, kc = (f4 & 7) * 4;
            union { __nv_bfloat16 e[4]; uint2 u; } hh, ll;
            hilo(pa[it].x, hh.e[0], ll.e[0]);
            hilo(pa[it].y, hh.e[1], ll.e[1]);
            hilo(pa[it].z, hh.e[2], ll.e[2]);
            hilo(pa[it].w, hh.e[3], ll.e[3]);
            *reinterpret_cast<uint2*>(sm + AH + m * (A_STR * 2) + kc * 2) = hh.u;
            *reinterpret_cast<uint2*>(sm + AL + m * (A_STR * 2) + kc * 2) = ll.u;
            const int k = f4 >> 5, nc = (f4 & 31) * 4;
            *reinterpret_cast<uint2*>(sm + BH + k * (B1_STR * 2) + nc * 2) = pbh[it];
            *reinterpret_cast<uint2*>(sm + BL + k * (B1_STR * 2) + nc * 2) = pbl[it];
        }
        __syncthreads();

        if (c < 15) K1_LOAD(c + 1);

#pragma unroll
        for (int ks = 0; ks < 32; ks += 16) {
            uint32_t ah[4][4], al_[4][4];
#pragma unroll
            for (int mi = 0; mi < 4; mi++) {
                const uint32_t off =
                    ((wm * 64 + mi * 16 + (lane & 15)) * A_STR + ks + (lane >> 4) * 8) * 2;
                ldsm4(ah[mi],  su + AH + off);
                ldsm4(al_[mi], su + AL + off);
            }
            uint32_t bh[2][4], bl[2][4];
#pragma unroll
            for (int p = 0; p < 2; p++) {
                const uint32_t off =
                    ((ks + (lane & 15)) * B1_STR + wn * 32 + p * 16 + (lane >> 4) * 8) * 2;
                ldsm4t(bh[p], su + BH + off);
                ldsm4t(bl[p], su + BL + off);
            }
#pragma unroll
            for (int mi = 0; mi < 4; mi++)
#pragma unroll
                for (int p = 0; p < 2; p++)
#pragma unroll
                    for (int ns = 0; ns < 2; ns++) {
                        const int ni = p * 2 + ns;
                        mma16816(acc[mi][ni], ah[mi],  bh[p][2 * ns], bh[p][2 * ns + 1]);
                        mma16816(acc[mi][ni], ah[mi],  bl[p][2 * ns], bl[p][2 * ns + 1]);
                        mma16816(acc[mi][ni], al_[mi], bh[p][2 * ns], bh[p][2 * ns + 1]);
                    }
        }
        __syncthreads();
    }

    float* Csm = reinterpret_cast<float*>(sm);
#pragma unroll
    for (int mi = 0; mi < 4; mi++)
#pragma unroll
        for (int ni = 0; ni < 4; ni++) {
            const int row = wm * 64 + mi * 16 + (lane >> 2);
            const int col = wn * 32 + ni * 8 + (lane & 3) * 2;
            *reinterpret_cast<float2*>(&Csm[row * 132 + col]) =
                make_float2(acc[mi][ni][0], acc[mi][ni][1]);
            *reinterpret_cast<float2*>(&Csm[(row + 8) * 132 + col]) =
                make_float2(acc[mi][ni][2], acc[mi][ni][3]);
        }
    __syncthreads();

    {
        const int row  = tid >> 1;
        const int half = tid & 1;
        const float* base = &Csm[row * 132 + half * 64];
        float4 v[16];
        float s = 0.f, ss = 0.f;
#pragma unroll
        for (int j = 0; j < 16; j++) {
            v[j] = *reinterpret_cast<const float4*>(base + j * 4);
            s  += v[j].x + v[j].y + v[j].z + v[j].w;
            ss += v[j].x * v[j].x + v[j].y * v[j].y + v[j].z * v[j].z + v[j].w * v[j].w;
        }
        const float mean = s * (1.0f / NIC);
        const float var  = ss * (1.0f / NIC) - mean * mean;
        const float inv  = rsqrtf(var + LN_EPS);
        const float* gam = half ? gamma_h : gamma_f;
        const float* bet = half ? beta_h  : beta_f;
        float* dst = (half ? d_Hs : d_G) + (size_t)(row0 + row) * NIC;
#pragma unroll
        for (int j = 0; j < 16; j++) {
            const float4 g4 = *reinterpret_cast<const float4*>(gam + j * 4);
            const float4 b4 = *reinterpret_cast<const float4*>(bet + j * 4);
            float4 o;
            o.x = (v[j].x - mean) * inv * g4.x + b4.x;
            o.y = (v[j].y - mean) * inv * g4.y + b4.y;
            o.z = (v[j].z - mean) * inv * g4.z + b4.z;
            o.w = (v[j].w - mean) * inv * g4.w + b4.w;
            *reinterpret_cast<float4*>(dst + j * 4) = o;
        }
    }
#undef K1_LOAD
}

// ---------------------------------------------------------------------------
// K2: P = softmax_h( G[b,w,h,i] * G[b,h,w,i] ) * H  -> bf16 hi/lo planes
// ---------------------------------------------------------------------------
__global__ __launch_bounds__(256)
void k2_softmax()
{
    __shared__ float red[4][64];
    const int tid = threadIdx.x;
    const int b   = blockIdx.x >> 6;
    const int w   = blockIdx.x & 63;
    const int i   = tid & 63;
    const int q   = tid >> 6;
    const int h0  = q * 16;

    float l[16];
#pragma unroll
    for (int hh = 0; hh < 16; hh++) {
        const int h = h0 + hh;
        const float gw = d_G[((size_t)((b * NH + w) * NW + h)) * NIC + i];
        const float gc = d_G[((size_t)((b * NH + h) * NW + w)) * NIC + i];
        l[hh] = gw * gc;
    }
    float m = l[0];
#pragma unroll
    for (int hh = 1; hh < 16; hh++) m = fmaxf(m, l[hh]);
    red[q][i] = m;
    __syncthreads();
    const float M = fmaxf(fmaxf(red[0][i], red[1][i]), fmaxf(red[2][i], red[3][i]));
    __syncthreads();

    float s = 0.0f;
#pragma unroll
    for (int hh = 0; hh < 16; hh++) {
        const float e = __expf(l[hh] - M);
        l[hh] = e;
        s += e;
    }
    red[q][i] = s;
    __syncthreads();
    const float S    = red[0][i] + red[1][i] + red[2][i] + red[3][i];
    const float rinv = 1.0f / S;

#pragma unroll
    for (int hh = 0; hh < 16; hh++) {
        const int h = h0 + hh;
        const size_t o = ((size_t)((b * NH + h) * NW + w)) * NIC + i;
        const float v = l[hh] * rinv * d_Hs[o];
        __nv_bfloat16 ph, pl; hilo(v, ph, pl);
        d_Phi[o] = ph;
        d_Plo[o] = pl;
    }
}

// ---------------------------------------------------------------------------
// K3 v2: out = x + LN_fgh(P @ w_fgh) * scale — B-RESIDENT persistent tiles.
// Grid 1024 CTAs x 2 M-tiles of 32 rows. Full K=64 of w_fgh hi/lo lives in
// smem (loaded once per CTA); mainloop has no global loads. Epilogue LN is
// direct-from-registers: quad shfl + red[32][8][2] cross-warp combine.
//
// smem bytes: AH 0(5632) | AL 5632 | BH 11264(66560) | BL 77824(66560)
//             | red 144384(2048) | gbuf 146432(4096)  -> total 150528
// ---------------------------------------------------------------------------
#define K3_SMEM 150528
#define A3_STR 88     // 176B rows: 16B-aligned, ldmatrix bank-disjoint
#define B3_STR 520    // 1040B rows: 16B-aligned, bank-disjoint

__global__ __launch_bounds__(256, 1)
void k3_mma(const float* __restrict__ gamma, const float* __restrict__ beta,
            const float* __restrict__ scale,
            const float* __restrict__ x, float* __restrict__ out)
{
    extern __shared__ char sm[];
    const uint32_t su = smem_u32(sm);
    const int AH = 0, AL = 5632, BH = 11264, BL = 77824;
    float (*red)[8][2] = reinterpret_cast<float (*)[8][2]>(sm + 144384);
    float* gbuf        = reinterpret_cast<float*>(sm + 146432);

    const int tid  = threadIdx.x;
    const int wid  = tid >> 5;       // warp n-block (64 cols)
    const int lane = tid & 31;
    const float sc = scale[0];

    // ---- one-time: gamma/beta + full B hi/lo into smem ----
    if (tid < 128) {
        const float4 g4 = *reinterpret_cast<const float4*>(gamma + tid * 4);
        const float4 b4 = *reinterpret_cast<const float4*>(beta  + tid * 4);
        *reinterpret_cast<float4*>(gbuf + tid * 4)       = g4;
        *reinterpret_cast<float4*>(gbuf + 512 + tid * 4) = b4;
    }
#pragma unroll
    for (int it = 0; it < 16; it++) {            // 4096 uint4 per plane
        const int f  = tid + it * 256;
        const int k  = f >> 6;                   // 0..63
        const int n8 = (f & 63) * 8;             // 0..504
        *reinterpret_cast<uint4*>(sm + BH + (k * B3_STR + n8) * 2) =
            *reinterpret_cast<const uint4*>(d_FH + k * NC + n8);
        *reinterpret_cast<uint4*>(sm + BL + (k * B3_STR + n8) * 2) =
            *reinterpret_cast<const uint4*>(d_FL + k * NC + n8);
    }

    for (int t = 0; t < 2; t++) {
        const int row0 = (blockIdx.x * 2 + t) * 32;

        // ---- A tile: P hi/lo 32x64 ----
#pragma unroll
        for (int it = 0; it < 2; it++) {
            const int f4 = tid + it * 256;       // 0..511
            const int m  = f4 >> 4;              // 0..31
            const int kc = (f4 & 15) * 4;        // 0..60
            const size_t go = (size_t)(row0 + m) * NIC + kc;
            *reinterpret_cast<uint2*>(sm + AH + (m * A3_STR + kc) * 2) =
                *reinterpret_cast<const uint2*>(d_Phi + go);
            *reinterpret_cast<uint2*>(sm + AL + (m * A3_STR + kc) * 2) =
                *reinterpret_cast<const uint2*>(d_Plo + go);
        }
        __syncthreads();   // covers B/gbuf (t=0), A (always), red reuse (t=1)

        // ---- mma over K=64, all-smem ----
        float acc[2][8][4];
#pragma unroll
        for (int mi = 0; mi < 2; mi++)
#pragma unroll
            for (int ni = 0; ni < 8; ni++)
#pragma unroll
                for (int q = 0; q < 4; q++) acc[mi][ni][q] = 0.0f;

#pragma unroll
        for (int ks = 0; ks < 64; ks += 16) {
            uint32_t ah[2][4], al_[2][4];
#pragma unroll
            for (int mi = 0; mi < 2; mi++) {
                const uint32_t off =
                    ((mi * 16 + (lane & 15)) * A3_STR + ks + (lane >> 4) * 8) * 2;
                ldsm4(ah[mi],  su + AH + off);
                ldsm4(al_[mi], su + AL + off);
            }
            uint32_t bh[4][4], bl[4][4];
#pragma unroll
            for (int p = 0; p < 4; p++) {
                const uint32_t off =
                    ((ks + (lane & 15)) * B3_STR + wid * 64 + p * 16 + (lane >> 4) * 8) * 2;
                ldsm4t(bh[p], su + BH + off);
                ldsm4t(bl[p], su + BL + off);
            }
#pragma unroll
            for (int mi = 0; mi < 2; mi++)
#pragma unroll
                for (int p = 0; p < 4; p++)
#pragma unroll
                    for (int ns = 0; ns < 2; ns++) {
                        const int ni = p * 2 + ns;
                        mma16816(acc[mi][ni], ah[mi],  bh[p][2 * ns], bh[p][2 * ns + 1]);
                        mma16816(acc[mi][ni], ah[mi],  bl[p][2 * ns], bl[p][2 * ns + 1]);
                        mma16816(acc[mi][ni], al_[mi], bh[p][2 * ns], bh[p][2 * ns + 1]);
                    }
        }

        // ---- LN reduction direct from registers ----
        // lane's 4 row-slots: slot = mi*2+half -> row mi*16 + (lane>>2) + half*8
        float s4[4], ss4[4];
#pragma unroll
        for (int slot = 0; slot < 4; slot++) {
            const int mi = slot >> 1, half = slot & 1;
            float s = 0.f, ss = 0.f;
#pragma unroll
            for (int ni = 0; ni < 8; ni++) {
                const float v0 = acc[mi][ni][half * 2];
                const float v1 = acc[mi][ni][half * 2 + 1];
                s += v0 + v1; ss += v0 * v0 + v1 * v1;
            }
#pragma unroll
            for (int o = 1; o < 4; o <<= 1) {
                s  += __shfl_xor_sync(0xffffffffu, s,  o);
                ss += __shfl_xor_sync(0xffffffffu, ss, o);
            }
            s4[slot] = s; ss4[slot] = ss;
        }
        if ((lane & 3) == 0) {
#pragma unroll
            for (int slot = 0; slot < 4; slot++) {
                const int r = (slot >> 1) * 16 + (lane >> 2) + (slot & 1) * 8;
                red[r][wid][0] = s4[slot];
                red[r][wid][1] = ss4[slot];
            }
        }
        __syncthreads();

        float mean[4], inv[4];
#pragma unroll
        for (int slot = 0; slot < 4; slot++) {
            const int r = (slot >> 1) * 16 + (lane >> 2) + (slot & 1) * 8;
            float S = 0.f, SS = 0.f;
#pragma unroll
            for (int w8 = 0; w8 < 8; w8++) { S += red[r][w8][0]; SS += red[r][w8][1]; }
            const float m = S * (1.0f / NC);
            mean[slot] = m;
            inv[slot]  = rsqrtf(SS * (1.0f / NC) - m * m + LN_EPS);
        }

        // ---- apply + residual, write out ----
#pragma unroll
        for (int mi = 0; mi < 2; mi++)
#pragma unroll
            for (int ni = 0; ni < 8; ni++) {
                const int col = wid * 64 + ni * 8 + (lane & 3) * 2;
                const float g0 = gbuf[col],       g1 = gbuf[col + 1];
                const float b0 = gbuf[512 + col], b1 = gbuf[512 + col + 1];
#pragma unroll
                for (int half = 0; half < 2; half++) {
                    const int slot = mi * 2 + half;
                    const int r = row0 + mi * 16 + (lane >> 2) + half * 8;
                    const float2 x2 = *reinterpret_cast<const float2*>(
                        x + (size_t)r * NC + col);
                    float2 o;
                    o.x = x2.x + ((acc[mi][ni][half * 2]     - mean[slot]) * inv[slot] * g0 + b0) * sc;
                    o.y = x2.y + ((acc[mi][ni][half * 2 + 1] - mean[slot]) * inv[slot] * g1 + b1) * sc;
                    *reinterpret_cast<float2*>(out + (size_t)r * NC + col) = o;
                }
            }
        // loop-start __syncthreads orders red reuse vs next tile
    }
}

// ---------------------------------------------------------------------------
// Launch. Inputs: 0:x 1:w_f 2:w_h 3:w_fgh 4:gamma_f 5:beta_f 6:gamma_h
// 7:beta_h 8:gamma_fgh 9:beta_fgh 10:scale
// ---------------------------------------------------------------------------
extern "C" void kernel_launch(void* const* d_in, const int* in_sizes, int n_in,
                              void* d_out, int out_size)
{
    (void)in_sizes; (void)n_in; (void)out_size;
    const float* x         = (const float*)d_in[0];
    const float* w_f       = (const float*)d_in[1];
    const float* w_h       = (const float*)d_in[2];
    const float* w_fgh     = (const float*)d_in[3];
    const float* gamma_f   = (const float*)d_in[4];
    const float* beta_f    = (const float*)d_in[5];
    const float* gamma_h   = (const float*)d_in[6];
    const float* beta_h    = (const float*)d_in[7];
    const float* gamma_fgh = (const float*)d_in[8];
    const float* beta_fgh  = (const float*)d_in[9];
    const float* scale     = (const float*)d_in[10];
    float* out             = (float*)d_out;

    cudaFuncSetAttribute(k1_mma, cudaFuncAttributeMaxDynamicSharedMemorySize, K1_SMEM);
    cudaFuncSetAttribute(k3_mma, cudaFuncAttributeMaxDynamicSharedMemorySize, K3_SMEM);

    k0_prep<<<384, 256>>>(w_f, w_h, w_fgh);
    k1_mma<<<NROWS / 128, 256, K1_SMEM>>>(x, gamma_f, beta_f, gamma_h, beta_h);
    k2_softmax<<<NB * NW, 256>>>();
    k3_mma<<<NROWS / 64, 256, K3_SMEM>>>(gamma_fgh, beta_fgh, scale, x, out);
}

// round 10
// speedup vs baseline: 1.8628x; 1.0814x over previous
#include <cuda_runtime.h>
#include <cuda_bf16.h>
#include <cstdint>
#include <cstddef>

// ---------------------------------------------------------------------------
// Problem constants
// ---------------------------------------------------------------------------
#define NB   16
#define NH   64
#define NW   64
#define NC   512
#define NIC  64
#define NROWS (NB*NH*NW)          // 65536
#define LN_EPS 1e-3f

// Scratch (device globals = sanctioned no-alloc scratch)
__device__ float d_G [(size_t)NROWS * NIC];
__device__ float d_Hs[(size_t)NROWS * NIC];
__device__ __nv_bfloat16 d_Phi[(size_t)NROWS * NIC];
__device__ __nv_bfloat16 d_Plo[(size_t)NROWS * NIC];
// Pre-split weights: [wf|wh] as [512][128], w_fgh as [64][512]
__device__ __nv_bfloat16 d_WH[512 * 128];
__device__ __nv_bfloat16 d_WL[512 * 128];
__device__ __nv_bfloat16 d_FH[64 * 512];
__device__ __nv_bfloat16 d_FL[64 * 512];

// ---------------------------------------------------------------------------
// Helpers (sm_80-family tensor path: mma.sync + ldmatrix + cp.async)
// ---------------------------------------------------------------------------
__device__ __forceinline__ uint32_t smem_u32(const void* p) {
    uint32_t a;
    asm("{ .reg .u64 t; cvta.to.shared.u64 t, %1; cvt.u32.u64 %0, t; }"
        : "=r"(a) : "l"(p));
    return a;
}
__device__ __forceinline__ void ldsm4(uint32_t r[4], uint32_t a) {
    asm volatile("ldmatrix.sync.aligned.m8n8.x4.shared.b16 {%0,%1,%2,%3}, [%4];"
                 : "=r"(r[0]), "=r"(r[1]), "=r"(r[2]), "=r"(r[3]) : "r"(a));
}
__device__ __forceinline__ void ldsm4t(uint32_t r[4], uint32_t a) {
    asm volatile("ldmatrix.sync.aligned.m8n8.x4.trans.shared.b16 {%0,%1,%2,%3}, [%4];"
                 : "=r"(r[0]), "=r"(r[1]), "=r"(r[2]), "=r"(r[3]) : "r"(a));
}
__device__ __forceinline__ void mma16816(float c[4], const uint32_t a[4],
                                         uint32_t b0, uint32_t b1) {
    asm volatile(
        "mma.sync.aligned.m16n8k16.row.col.f32.bf16.bf16.f32 "
        "{%0,%1,%2,%3}, {%4,%5,%6,%7}, {%8,%9}, {%0,%1,%2,%3};"
        : "+f"(c[0]), "+f"(c[1]), "+f"(c[2]), "+f"(c[3])
        : "r"(a[0]), "r"(a[1]), "r"(a[2]), "r"(a[3]), "r"(b0), "r"(b1));
}
__device__ __forceinline__ void hilo(float v, __nv_bfloat16& h, __nv_bfloat16& l) {
    h = __float2bfloat16(v);
    l = __float2bfloat16(v - __bfloat162float(h));
}
__device__ __forceinline__ void cp_a8(uint32_t s, const void* g) {
    asm volatile("cp.async.ca.shared.global [%0], [%1], 8;" :: "r"(s), "l"(g) : "memory");
}
__device__ __forceinline__ void cp_a16(uint32_t s, const void* g) {
    asm volatile("cp.async.cg.shared.global [%0], [%1], 16;" :: "r"(s), "l"(g) : "memory");
}
#define CP_COMMIT()  asm volatile("cp.async.commit_group;" ::: "memory")
#define CP_WAIT(n)   asm volatile("cp.async.wait_group %0;" :: "n"(n) : "memory")

// ---------------------------------------------------------------------------
// K0: pre-split weights to bf16 hi/lo.
// ---------------------------------------------------------------------------
__global__ __launch_bounds__(256)
void k0_prep(const float* __restrict__ wf, const float* __restrict__ wh,
             const float* __restrict__ wfgh)
{
    const int id = blockIdx.x * 256 + threadIdx.x;
    if (id < 512 * 128) {
        const int k = id >> 7, n = id & 127;
        const float v = (n < NIC) ? wf[k * NIC + n] : wh[k * NIC + (n - NIC)];
        __nv_bfloat16 h, l; hilo(v, h, l);
        d_WH[id] = h; d_WL[id] = l;
    } else {
        const int id2 = id - 512 * 128;
        __nv_bfloat16 h, l; hilo(wfgh[id2], h, l);
        d_FH[id2] = h; d_FL[id2] = l;
    }
}

// ---------------------------------------------------------------------------
// K1 v2: 512 threads (16 warps, 4x4 warp grid, 32x32 warp tiles).
// CTA 128(M) x 128(N), K-chunk 32, 16 chunks, register prefetch.
// Direct-from-registers LN epilogue (no C staging).
// Static smem 43008 B: AH 0 | AL 10240 | BH 20480 | BL 29184 |
//                      red 37888 (128x4x2 f32) | gbuf 41984 (256 f32)
// ---------------------------------------------------------------------------
#define A_STR 40
#define B1_STR 136

__global__ __launch_bounds__(512, 1)
void k1_mma(const float* __restrict__ x,
            const float* __restrict__ gamma_f, const float* __restrict__ beta_f,
            const float* __restrict__ gamma_h, const float* __restrict__ beta_h)
{
    __shared__ __align__(16) unsigned char sm[43008];
    const uint32_t su = smem_u32(sm);
    const int AH = 0, AL = 10240, BH = 20480, BL = 29184;
    float (*red)[4][2] = reinterpret_cast<float (*)[4][2]>(sm + 37888);
    float* gbuf        = reinterpret_cast<float*>(sm + 41984);

    const int tid  = threadIdx.x;
    const int wid  = tid >> 5;
    const int lane = tid & 31;
    const int wm   = wid & 3;        // M warp-block (32 rows)
    const int wn   = wid >> 2;       // N warp-block (32 cols)
    const int row0 = blockIdx.x * 128;

    if (tid < 64) {
        gbuf[tid]       = gamma_f[tid];
        gbuf[64 + tid]  = beta_f[tid];
        gbuf[128 + tid] = gamma_h[tid];
        gbuf[192 + tid] = beta_h[tid];
    }

    float acc[2][4][4];
#pragma unroll
    for (int mi = 0; mi < 2; mi++)
#pragma unroll
        for (int ni = 0; ni < 4; ni++)
#pragma unroll
            for (int q = 0; q < 4; q++) acc[mi][ni][q] = 0.0f;

    float4 pa[2];
    uint2  pbh[2], pbl[2];

#define K1_LOAD(c) do {                                                          \
    _Pragma("unroll")                                                            \
    for (int it = 0; it < 2; it++) {                                             \
        const int f4 = tid + it * 512;                                           \
        const int m  = f4 >> 3, kc = (f4 & 7) * 4;                               \
        pa[it] = *reinterpret_cast<const float4*>(                               \
            x + (size_t)(row0 + m) * NC + (c) * 32 + kc);                        \
        const int k = f4 >> 5, nc = (f4 & 31) * 4;                               \
        pbh[it] = *reinterpret_cast<const uint2*>(d_WH + ((c) * 32 + k) * 128 + nc); \
        pbl[it] = *reinterpret_cast<const uint2*>(d_WL + ((c) * 32 + k) * 128 + nc); \
    } } while (0)

    K1_LOAD(0);

    for (int c = 0; c < 16; c++) {
        // store prefetched chunk (convert A to hi/lo)
#pragma unroll
        for (int it = 0; it < 2; it++) {
            const int f4 = tid + it * 512;
            const int m  = f4 >> 3, kc = (f4 & 7) * 4;
            union { __nv_bfloat16 e[4]; uint2 u; } hh, ll;
            hilo(pa[it].x, hh.e[0], ll.e[0]);
            hilo(pa[it].y, hh.e[1], ll.e[1]);
            hilo(pa[it].z, hh.e[2], ll.e[2]);
            hilo(pa[it].w, hh.e[3], ll.e[3]);
            *reinterpret_cast<uint2*>(sm + AH + (m * A_STR + kc) * 2) = hh.u;
            *reinterpret_cast<uint2*>(sm + AL + (m * A_STR + kc) * 2) = ll.u;
            const int k = f4 >> 5, nc = (f4 & 31) * 4;
            *reinterpret_cast<uint2*>(sm + BH + (k * B1_STR + nc) * 2) = pbh[it];
            *reinterpret_cast<uint2*>(sm + BL + (k * B1_STR + nc) * 2) = pbl[it];
        }
        __syncthreads();

        if (c < 15) K1_LOAD(c + 1);

#pragma unroll
        for (int ks = 0; ks < 32; ks += 16) {
            uint32_t ah[2][4], al_[2][4];
#pragma unroll
            for (int mi = 0; mi < 2; mi++) {
                const uint32_t off =
                    ((wm * 32 + mi * 16 + (lane & 15)) * A_STR + ks + (lane >> 4) * 8) * 2;
                ldsm4(ah[mi],  su + AH + off);
                ldsm4(al_[mi], su + AL + off);
            }
            uint32_t bh[2][4], bl[2][4];
#pragma unroll
            for (int p = 0; p < 2; p++) {
                const uint32_t off =
                    ((ks + (lane & 15)) * B1_STR + wn * 32 + p * 16 + (lane >> 4) * 8) * 2;
                ldsm4t(bh[p], su + BH + off);
                ldsm4t(bl[p], su + BL + off);
            }
#pragma unroll
            for (int mi = 0; mi < 2; mi++)
#pragma unroll
                for (int p = 0; p < 2; p++)
#pragma unroll
                    for (int ns = 0; ns < 2; ns++) {
                        const int ni = p * 2 + ns;
                        mma16816(acc[mi][ni], ah[mi],  bh[p][2 * ns], bh[p][2 * ns + 1]);
                        mma16816(acc[mi][ni], ah[mi],  bl[p][2 * ns], bl[p][2 * ns + 1]);
                        mma16816(acc[mi][ni], al_[mi], bh[p][2 * ns], bh[p][2 * ns + 1]);
                    }
        }
        __syncthreads();
    }
#undef K1_LOAD

    // ---- LN reduction direct from registers ----
#pragma unroll
    for (int mi = 0; mi < 2; mi++)
#pragma unroll
        for (int half = 0; half < 2; half++) {
            float s = 0.f, ss = 0.f;
#pragma unroll
            for (int ni = 0; ni < 4; ni++) {
                const float v0 = acc[mi][ni][half * 2];
                const float v1 = acc[mi][ni][half * 2 + 1];
                s += v0 + v1; ss += v0 * v0 + v1 * v1;
            }
#pragma unroll
            for (int o = 1; o < 4; o <<= 1) {
                s  += __shfl_xor_sync(0xffffffffu, s,  o);
                ss += __shfl_xor_sync(0xffffffffu, ss, o);
            }
            if ((lane & 3) == 0) {
                const int r = wm * 32 + mi * 16 + (lane >> 2) + half * 8;
                red[r][wn][0] = s;
                red[r][wn][1] = ss;
            }
        }
    __syncthreads();

    // ---- apply: combine 2 N-warps per 64-half, write d_G / d_Hs ----
    const int sel  = wn >> 1;             // 0 = f-half, 1 = h-half
    const int base = sel * 2;
    float* dstB = sel ? d_Hs : d_G;
#pragma unroll
    for (int mi = 0; mi < 2; mi++)
#pragma unroll
        for (int half = 0; half < 2; half++) {
            const int r  = wm * 32 + mi * 16 + (lane >> 2) + half * 8;
            const float S  = red[r][base][0] + red[r][base + 1][0];
            const float SS = red[r][base][1] + red[r][base + 1][1];
            const float mean = S * (1.0f / NIC);
            const float inv  = rsqrtf(SS * (1.0f / NIC) - mean * mean + LN_EPS);
            float* dst = dstB + (size_t)(row0 + r) * NIC;
#pragma unroll
            for (int ni = 0; ni < 4; ni++) {
                const int col = (wn & 1) * 32 + ni * 8 + (lane & 3) * 2;
                const float g0 = gbuf[sel * 128 + col];
                const float g1 = gbuf[sel * 128 + col + 1];
                const float b0 = gbuf[sel * 128 + 64 + col];
                const float b1 = gbuf[sel * 128 + 64 + col + 1];
                float2 o;
                o.x = (acc[mi][ni][half * 2]     - mean) * inv * g0 + b0;
                o.y = (acc[mi][ni][half * 2 + 1] - mean) * inv * g1 + b1;
                *reinterpret_cast<float2*>(dst + col) = o;
            }
        }
}

// ---------------------------------------------------------------------------
// K2: P = softmax_h( G[b,w,h,i] * G[b,h,w,i] ) * H  -> bf16 hi/lo planes
// ---------------------------------------------------------------------------
__global__ __launch_bounds__(256)
void k2_softmax()
{
    __shared__ float red[4][64];
    const int tid = threadIdx.x;
    const int b   = blockIdx.x >> 6;
    const int w   = blockIdx.x & 63;
    const int i   = tid & 63;
    const int q   = tid >> 6;
    const int h0  = q * 16;

    float l[16];
#pragma unroll
    for (int hh = 0; hh < 16; hh++) {
        const int h = h0 + hh;
        const float gw = d_G[((size_t)((b * NH + w) * NW + h)) * NIC + i];
        const float gc = d_G[((size_t)((b * NH + h) * NW + w)) * NIC + i];
        l[hh] = gw * gc;
    }
    float m = l[0];
#pragma unroll
    for (int hh = 1; hh < 16; hh++) m = fmaxf(m, l[hh]);
    red[q][i] = m;
    __syncthreads();
    const float M = fmaxf(fmaxf(red[0][i], red[1][i]), fmaxf(red[2][i], red[3][i]));
    __syncthreads();

    float s = 0.0f;
#pragma unroll
    for (int hh = 0; hh < 16; hh++) {
        const float e = __expf(l[hh] - M);
        l[hh] = e;
        s += e;
    }
    red[q][i] = s;
    __syncthreads();
    const float S    = red[0][i] + red[1][i] + red[2][i] + red[3][i];
    const float rinv = 1.0f / S;

#pragma unroll
    for (int hh = 0; hh < 16; hh++) {
        const int h = h0 + hh;
        const size_t o = ((size_t)((b * NH + h) * NW + w)) * NIC + i;
        const float v = l[hh] * rinv * d_Hs[o];
        __nv_bfloat16 ph, pl; hilo(v, ph, pl);
        d_Phi[o] = ph;
        d_Plo[o] = pl;
    }
}

// ---------------------------------------------------------------------------
// K3 v3: 512 threads (16 warps = 2 M-warps x 8 N-warps), B-resident,
// 4 tiles of 32 rows per CTA (grid 512), cp.async double-buffered A.
// smem: A buf0 0 (AH|AL 5632 each) | A buf1 11264 | BH 22528 | BL 89088 |
//       red 155648 (32x8x2) | gbuf 157696 (1024 f32)  -> 161792 bytes
// ---------------------------------------------------------------------------
#define K3_SMEM 161792
#define A3_STR 88
#define B3_STR 520

__global__ __launch_bounds__(512, 1)
void k3_mma(const float* __restrict__ gamma, const float* __restrict__ beta,
            const float* __restrict__ scale,
            const float* __restrict__ x, float* __restrict__ out)
{
    extern __shared__ char sm[];
    const uint32_t su = smem_u32(sm);
    const int ABUF = 11264;                  // per-buffer bytes (AH + AL)
    const int BH = 22528, BL = 89088;
    float (*red)[8][2] = reinterpret_cast<float (*)[8][2]>(sm + 155648);
    float* gbuf        = reinterpret_cast<float*>(sm + 157696);

    const int tid  = threadIdx.x;
    const int wid  = tid >> 5;
    const int lane = tid & 31;
    const int wn   = wid & 7;                // N warp-block (64 cols)
    const int wm2  = wid >> 3;               // M warp-block (16 rows)
    const float sc = scale[0];

    const int am = tid >> 4;                 // A-load row 0..31
    const int ak = (tid & 15) * 4;           // A-load k 0..60

    if (tid < 128) {
        *reinterpret_cast<float4*>(gbuf + tid * 4) =
            *reinterpret_cast<const float4*>(gamma + tid * 4);
        *reinterpret_cast<float4*>(gbuf + 512 + tid * 4) =
            *reinterpret_cast<const float4*>(beta + tid * 4);
    }
    // B (one-time, 16B cg cp.async)
#pragma unroll
    for (int it = 0; it < 8; it++) {
        const int f  = tid + it * 512;
        const int k  = f >> 6;
        const int n8 = (f & 63) * 8;
        cp_a16(su + BH + (k * B3_STR + n8) * 2, d_FH + k * NC + n8);
        cp_a16(su + BL + (k * B3_STR + n8) * 2, d_FL + k * NC + n8);
    }
    // A tile 0
    {
        const int r0 = blockIdx.x * 4 * 32;
        const size_t go = (size_t)(r0 + am) * NIC + ak;
        cp_a8(su + (am * A3_STR + ak) * 2, d_Phi + go);
        cp_a8(su + 5632 + (am * A3_STR + ak) * 2, d_Plo + go);
    }
    CP_COMMIT();   // G0 = B + A0

    for (int t = 0; t < 4; t++) {
        const int row0 = (blockIdx.x * 4 + t) * 32;

        if (t < 3) {   // prefetch next A tile into the other buffer
            const int nb = ((t + 1) & 1) * ABUF;
            const size_t go = (size_t)(row0 + 32 + am) * NIC + ak;
            cp_a8(su + nb + (am * A3_STR + ak) * 2, d_Phi + go);
            cp_a8(su + nb + 5632 + (am * A3_STR + ak) * 2, d_Plo + go);
            CP_COMMIT();
            CP_WAIT(1);
        } else {
            CP_WAIT(0);
        }
        __syncthreads();

        const int AHo = (t & 1) * ABUF;
        const int ALo = AHo + 5632;

        float acc[8][4];
#pragma unroll
        for (int ni = 0; ni < 8; ni++)
#pragma unroll
            for (int q = 0; q < 4; q++) acc[ni][q] = 0.0f;

#pragma unroll
        for (int ks = 0; ks < 64; ks += 16) {
            uint32_t ah[4], al_[4];
            {
                const uint32_t off =
                    ((wm2 * 16 + (lane & 15)) * A3_STR + ks + (lane >> 4) * 8) * 2;
                ldsm4(ah,  su + AHo + off);
                ldsm4(al_, su + ALo + off);
            }
            uint32_t bh[4][4], bl[4][4];
#pragma unroll
            for (int p = 0; p < 4; p++) {
                const uint32_t off =
                    ((ks + (lane & 15)) * B3_STR + wn * 64 + p * 16 + (lane >> 4) * 8) * 2;
                ldsm4t(bh[p], su + BH + off);
                ldsm4t(bl[p], su + BL + off);
            }
#pragma unroll
            for (int p = 0; p < 4; p++)
#pragma unroll
                for (int ns = 0; ns < 2; ns++) {
                    const int ni = p * 2 + ns;
                    mma16816(acc[ni], ah,  bh[p][2 * ns], bh[p][2 * ns + 1]);
                    mma16816(acc[ni], ah,  bl[p][2 * ns], bl[p][2 * ns + 1]);
                    mma16816(acc[ni], al_, bh[p][2 * ns], bh[p][2 * ns + 1]);
                }
        }

        // ---- LN reduction (quad shfl + 8-warp combine) ----
#pragma unroll
        for (int half = 0; half < 2; half++) {
            float s = 0.f, ss = 0.f;
#pragma unroll
            for (int ni = 0; ni < 8; ni++) {
                const float v0 = acc[ni][half * 2];
                const float v1 = acc[ni][half * 2 + 1];
                s += v0 + v1; ss += v0 * v0 + v1 * v1;
            }
#pragma unroll
            for (int o = 1; o < 4; o <<= 1) {
                s  += __shfl_xor_sync(0xffffffffu, s,  o);
                ss += __shfl_xor_sync(0xffffffffu, ss, o);
            }
            if ((lane & 3) == 0) {
                const int r = wm2 * 16 + (lane >> 2) + half * 8;
                red[r][wn][0] = s;
                red[r][wn][1] = ss;
            }
        }
        __syncthreads();

        float mean[2], inv[2];
#pragma unroll
        for (int half = 0; half < 2; half++) {
            const int r = wm2 * 16 + (lane >> 2) + half * 8;
            float S = 0.f, SS = 0.f;
#pragma unroll
            for (int w8 = 0; w8 < 8; w8++) { S += red[r][w8][0]; SS += red[r][w8][1]; }
            const float m = S * (1.0f / NC);
            mean[half] = m;
            inv[half]  = rsqrtf(SS * (1.0f / NC) - m * m + LN_EPS);
        }

        // ---- apply + residual ----
#pragma unroll
        for (int ni = 0; ni < 8; ni++) {
            const int col = wn * 64 + ni * 8 + (lane & 3) * 2;
            const float g0 = gbuf[col],       g1 = gbuf[col + 1];
            const float b0 = gbuf[512 + col], b1 = gbuf[512 + col + 1];
#pragma unroll
            for (int half = 0; half < 2; half++) {
                const int r = row0 + wm2 * 16 + (lane >> 2) + half * 8;
                const float2 x2 = *reinterpret_cast<const float2*>(
                    x + (size_t)r * NC + col);
                float2 o;
                o.x = x2.x + ((acc[ni][half * 2]     - mean[half]) * inv[half] * g0 + b0) * sc;
                o.y = x2.y + ((acc[ni][half * 2 + 1] - mean[half]) * inv[half] * g1 + b1) * sc;
                *reinterpret_cast<float2*>(out + (size_t)r * NC + col) = o;
            }
        }
    }
}

// ---------------------------------------------------------------------------
// Launch. Inputs: 0:x 1:w_f 2:w_h 3:w_fgh 4:gamma_f 5:beta_f 6:gamma_h
// 7:beta_h 8:gamma_fgh 9:beta_fgh 10:scale
// ---------------------------------------------------------------------------
extern "C" void kernel_launch(void* const* d_in, const int* in_sizes, int n_in,
                              void* d_out, int out_size)
{
    (void)in_sizes; (void)n_in; (void)out_size;
    const float* x         = (const float*)d_in[0];
    const float* w_f       = (const float*)d_in[1];
    const float* w_h       = (const float*)d_in[2];
    const float* w_fgh     = (const float*)d_in[3];
    const float* gamma_f   = (const float*)d_in[4];
    const float* beta_f    = (const float*)d_in[5];
    const float* gamma_h   = (const float*)d_in[6];
    const float* beta_h    = (const float*)d_in[7];
    const float* gamma_fgh = (const float*)d_in[8];
    const float* beta_fgh  = (const float*)d_in[9];
    const float* scale     = (const float*)d_in[10];
    float* out             = (float*)d_out;

    cudaFuncSetAttribute(k3_mma, cudaFuncAttributeMaxDynamicSharedMemorySize, K3_SMEM);

    k0_prep<<<384, 256>>>(w_f, w_h, w_fgh);
    k1_mma<<<NROWS / 128, 512>>>(x, gamma_f, beta_f, gamma_h, beta_h);
    k2_softmax<<<NB * NW, 256>>>();
    k3_mma<<<NROWS / 128, 512, K3_SMEM>>>(gamma_fgh, beta_fgh, scale, x, out);
}

// round 11
// speedup vs baseline: 1.9447x; 1.0440x over previous
#include <cuda_runtime.h>
#include <cuda_bf16.h>
#include <cstdint>
#include <cstddef>

// ---------------------------------------------------------------------------
// Problem constants
// ---------------------------------------------------------------------------
#define NB   16
#define NH   64
#define NW   64
#define NC   512
#define NIC  64
#define NROWS (NB*NH*NW)          // 65536
#define LN_EPS 1e-3f

// Scratch (device globals = sanctioned no-alloc scratch)
__device__ float d_G [(size_t)NROWS * NIC];
__device__ float d_Hs[(size_t)NROWS * NIC];
__device__ __nv_bfloat16 d_Phi[(size_t)NROWS * NIC];
__device__ __nv_bfloat16 d_Plo[(size_t)NROWS * NIC];
// Pre-split weights: [wf|wh] as [512][128], w_fgh as [64][512]
__device__ __nv_bfloat16 d_WH[512 * 128];
__device__ __nv_bfloat16 d_WL[512 * 128];
__device__ __nv_bfloat16 d_FH[64 * 512];
__device__ __nv_bfloat16 d_FL[64 * 512];

// ---------------------------------------------------------------------------
// Helpers (sm_80-family tensor path: mma.sync + ldmatrix + cp.async)
// ---------------------------------------------------------------------------
__device__ __forceinline__ uint32_t smem_u32(const void* p) {
    uint32_t a;
    asm("{ .reg .u64 t; cvta.to.shared.u64 t, %1; cvt.u32.u64 %0, t; }"
        : "=r"(a) : "l"(p));
    return a;
}
__device__ __forceinline__ void ldsm4(uint32_t r[4], uint32_t a) {
    asm volatile("ldmatrix.sync.aligned.m8n8.x4.shared.b16 {%0,%1,%2,%3}, [%4];"
                 : "=r"(r[0]), "=r"(r[1]), "=r"(r[2]), "=r"(r[3]) : "r"(a));
}
__device__ __forceinline__ void ldsm4t(uint32_t r[4], uint32_t a) {
    asm volatile("ldmatrix.sync.aligned.m8n8.x4.trans.shared.b16 {%0,%1,%2,%3}, [%4];"
                 : "=r"(r[0]), "=r"(r[1]), "=r"(r[2]), "=r"(r[3]) : "r"(a));
}
__device__ __forceinline__ void mma16816(float c[4], const uint32_t a[4],
                                         uint32_t b0, uint32_t b1) {
    asm volatile(
        "mma.sync.aligned.m16n8k16.row.col.f32.bf16.bf16.f32 "
        "{%0,%1,%2,%3}, {%4,%5,%6,%7}, {%8,%9}, {%0,%1,%2,%3};"
        : "+f"(c[0]), "+f"(c[1]), "+f"(c[2]), "+f"(c[3])
        : "r"(a[0]), "r"(a[1]), "r"(a[2]), "r"(a[3]), "r"(b0), "r"(b1));
}
__device__ __forceinline__ void hilo(float v, __nv_bfloat16& h, __nv_bfloat16& l) {
    h = __float2bfloat16(v);
    l = __float2bfloat16(v - __bfloat162float(h));
}
__device__ __forceinline__ void cp_a8(uint32_t s, const void* g) {
    asm volatile("cp.async.ca.shared.global [%0], [%1], 8;" :: "r"(s), "l"(g) : "memory");
}
__device__ __forceinline__ void cp_a16(uint32_t s, const void* g) {
    asm volatile("cp.async.cg.shared.global [%0], [%1], 16;" :: "r"(s), "l"(g) : "memory");
}
#define CP_COMMIT()  asm volatile("cp.async.commit_group;" ::: "memory")
#define CP_WAIT(n)   asm volatile("cp.async.wait_group %0;" :: "n"(n) : "memory")

// ---------------------------------------------------------------------------
// K0: pre-split weights to bf16 hi/lo.
// ---------------------------------------------------------------------------
__global__ __launch_bounds__(256)
void k0_prep(const float* __restrict__ wf, const float* __restrict__ wh,
             const float* __restrict__ wfgh)
{
    const int id = blockIdx.x * 256 + threadIdx.x;
    if (id < 512 * 128) {
        const int k = id >> 7, n = id & 127;
        const float v = (n < NIC) ? wf[k * NIC + n] : wh[k * NIC + (n - NIC)];
        __nv_bfloat16 h, l; hilo(v, h, l);
        d_WH[id] = h; d_WL[id] = l;
    } else {
        const int id2 = id - 512 * 128;
        __nv_bfloat16 h, l; hilo(wfgh[id2], h, l);
        d_FH[id2] = h; d_FL[id2] = l;
    }
}

// ---------------------------------------------------------------------------
// K1 v3: 512 threads, 4x4 warp grid, 32x32 warp tiles, CTA 128x128, BK=32.
// Double-buffered smem chunks (ONE sync per chunk), B via cp.async,
// A via register prefetch + fp32->bf16 hi/lo convert.
// Dynamic smem 80896: buf0 0 / buf1 37888 (each AH 10240|AL 10240|BH 8704|
// BL 8704) | red 75776 (128x4x2 f32) | gbuf 79872 (256 f32)
// ---------------------------------------------------------------------------
#define K1_SMEM 80896
#define K1_BUF  37888
#define A_STR 40
#define B1_STR 136

__global__ __launch_bounds__(512, 1)
void k1_mma(const float* __restrict__ x,
            const float* __restrict__ gamma_f, const float* __restrict__ beta_f,
            const float* __restrict__ gamma_h, const float* __restrict__ beta_h)
{
    extern __shared__ char sm[];
    const uint32_t su = smem_u32(sm);
    const int AH = 0, AL = 10240, BH = 20480, BL = 29184;
    float (*red)[4][2] = reinterpret_cast<float (*)[4][2]>(sm + 75776);
    float* gbuf        = reinterpret_cast<float*>(sm + 79872);

    const int tid  = threadIdx.x;
    const int wid  = tid >> 5;
    const int lane = tid & 31;
    const int wm   = wid & 3;        // M warp-block (32 rows)
    const int wn   = wid >> 2;       // N warp-block (32 cols)
    const int row0 = blockIdx.x * 128;

    if (tid < 64) {
        gbuf[tid]       = gamma_f[tid];
        gbuf[64 + tid]  = beta_f[tid];
        gbuf[128 + tid] = gamma_h[tid];
        gbuf[192 + tid] = beta_h[tid];
    }

    float acc[2][4][4];
#pragma unroll
    for (int mi = 0; mi < 2; mi++)
#pragma unroll
        for (int ni = 0; ni < 4; ni++)
#pragma unroll
            for (int q = 0; q < 4; q++) acc[mi][ni][q] = 0.0f;

    float4 pa[2];

    // ---- prolog: A(0) regs + B(0) cp.async into buf0 ----
#pragma unroll
    for (int it = 0; it < 2; it++) {
        const int f4 = tid + it * 512;
        const int m  = f4 >> 3, kc = (f4 & 7) * 4;
        pa[it] = *reinterpret_cast<const float4*>(x + (size_t)(row0 + m) * NC + kc);
    }
#pragma unroll
    for (int it = 0; it < 2; it++) {
        const int f4 = tid + it * 512;
        const int k  = f4 >> 5, nc = (f4 & 31) * 4;
        cp_a8(su + BH + (k * B1_STR + nc) * 2, d_WH + k * 128 + nc);
        cp_a8(su + BL + (k * B1_STR + nc) * 2, d_WL + k * 128 + nc);
    }
    CP_COMMIT();

    for (int c = 0; c < 16; c++) {
        const int bo = (c & 1) * K1_BUF;

        // ---- STS A(c) with hi/lo convert ----
#pragma unroll
        for (int it = 0; it < 2; it++) {
            const int f4 = tid + it * 512;
            const int m  = f4 >> 3, kc = (f4 & 7) * 4;
            union { __nv_bfloat16 e[4]; uint2 u; } hh, ll;
            hilo(pa[it].x, hh.e[0], ll.e[0]);
            hilo(pa[it].y, hh.e[1], ll.e[1]);
            hilo(pa[it].z, hh.e[2], ll.e[2]);
            hilo(pa[it].w, hh.e[3], ll.e[3]);
            *reinterpret_cast<uint2*>(sm + bo + AH + (m * A_STR + kc) * 2) = hh.u;
            *reinterpret_cast<uint2*>(sm + bo + AL + (m * A_STR + kc) * 2) = ll.u;
        }
        CP_WAIT(0);          // B(c) landed
        __syncthreads();     // buf[c&1] fully visible; all warps done mma(c-1)

        if (c < 15) {        // prefetch chunk c+1 into the other buffer
            const int nbo = ((c + 1) & 1) * K1_BUF;
#pragma unroll
            for (int it = 0; it < 2; it++) {
                const int f4 = tid + it * 512;
                const int m  = f4 >> 3, kc = (f4 & 7) * 4;
                pa[it] = *reinterpret_cast<const float4*>(
                    x + (size_t)(row0 + m) * NC + (c + 1) * 32 + kc);
            }
#pragma unroll
            for (int it = 0; it < 2; it++) {
                const int f4 = tid + it * 512;
                const int k  = f4 >> 5, nc = (f4 & 31) * 4;
                cp_a8(su + nbo + BH + (k * B1_STR + nc) * 2,
                      d_WH + ((c + 1) * 32 + k) * 128 + nc);
                cp_a8(su + nbo + BL + (k * B1_STR + nc) * 2,
                      d_WL + ((c + 1) * 32 + k) * 128 + nc);
            }
            CP_COMMIT();
        }

        // ---- tensor math on buf[c&1] ----
#pragma unroll
        for (int ks = 0; ks < 32; ks += 16) {
            uint32_t ah[2][4], al_[2][4];
#pragma unroll
            for (int mi = 0; mi < 2; mi++) {
                const uint32_t off =
                    ((wm * 32 + mi * 16 + (lane & 15)) * A_STR + ks + (lane >> 4) * 8) * 2;
                ldsm4(ah[mi],  su + bo + AH + off);
                ldsm4(al_[mi], su + bo + AL + off);
            }
            uint32_t bh[2][4], bl[2][4];
#pragma unroll
            for (int p = 0; p < 2; p++) {
                const uint32_t off =
                    ((ks + (lane & 15)) * B1_STR + wn * 32 + p * 16 + (lane >> 4) * 8) * 2;
                ldsm4t(bh[p], su + bo + BH + off);
                ldsm4t(bl[p], su + bo + BL + off);
            }
#pragma unroll
            for (int mi = 0; mi < 2; mi++)
#pragma unroll
                for (int p = 0; p < 2; p++)
#pragma unroll
                    for (int ns = 0; ns < 2; ns++) {
                        const int ni = p * 2 + ns;
                        mma16816(acc[mi][ni], ah[mi],  bh[p][2 * ns], bh[p][2 * ns + 1]);
                        mma16816(acc[mi][ni], ah[mi],  bl[p][2 * ns], bl[p][2 * ns + 1]);
                        mma16816(acc[mi][ni], al_[mi], bh[p][2 * ns], bh[p][2 * ns + 1]);
                    }
        }
        // no second sync: next STS targets the other buffer; sync(c+1)
        // guarantees all warps finished mma(c) before buf[c&1] is rewritten.
    }

    // ---- LN reduction direct from registers ----
#pragma unroll
    for (int mi = 0; mi < 2; mi++)
#pragma unroll
        for (int half = 0; half < 2; half++) {
            float s = 0.f, ss = 0.f;
#pragma unroll
            for (int ni = 0; ni < 4; ni++) {
                const float v0 = acc[mi][ni][half * 2];
                const float v1 = acc[mi][ni][half * 2 + 1];
                s += v0 + v1; ss += v0 * v0 + v1 * v1;
            }
#pragma unroll
            for (int o = 1; o < 4; o <<= 1) {
                s  += __shfl_xor_sync(0xffffffffu, s,  o);
                ss += __shfl_xor_sync(0xffffffffu, ss, o);
            }
            if ((lane & 3) == 0) {
                const int r = wm * 32 + mi * 16 + (lane >> 2) + half * 8;
                red[r][wn][0] = s;
                red[r][wn][1] = ss;
            }
        }
    __syncthreads();

    // ---- apply: combine 2 N-warps per 64-half, write d_G / d_Hs ----
    const int sel  = wn >> 1;
    const int base = sel * 2;
    float* dstB = sel ? d_Hs : d_G;
#pragma unroll
    for (int mi = 0; mi < 2; mi++)
#pragma unroll
        for (int half = 0; half < 2; half++) {
            const int r  = wm * 32 + mi * 16 + (lane >> 2) + half * 8;
            const float S  = red[r][base][0] + red[r][base + 1][0];
            const float SS = red[r][base][1] + red[r][base + 1][1];
            const float mean = S * (1.0f / NIC);
            const float inv  = rsqrtf(SS * (1.0f / NIC) - mean * mean + LN_EPS);
            float* dst = dstB + (size_t)(row0 + r) * NIC;
#pragma unroll
            for (int ni = 0; ni < 4; ni++) {
                const int col = (wn & 1) * 32 + ni * 8 + (lane & 3) * 2;
                const float g0 = gbuf[sel * 128 + col];
                const float g1 = gbuf[sel * 128 + col + 1];
                const float b0 = gbuf[sel * 128 + 64 + col];
                const float b1 = gbuf[sel * 128 + 64 + col + 1];
                float2 o;
                o.x = (acc[mi][ni][half * 2]     - mean) * inv * g0 + b0;
                o.y = (acc[mi][ni][half * 2 + 1] - mean) * inv * g1 + b1;
                *reinterpret_cast<float2*>(dst + col) = o;
            }
        }
}

// ---------------------------------------------------------------------------
// K2: P = softmax_h( G[b,w,h,i] * G[b,h,w,i] ) * H  -> bf16 hi/lo planes
// ---------------------------------------------------------------------------
__global__ __launch_bounds__(256)
void k2_softmax()
{
    __shared__ float red[4][64];
    const int tid = threadIdx.x;
    const int b   = blockIdx.x >> 6;
    const int w   = blockIdx.x & 63;
    const int i   = tid & 63;
    const int q   = tid >> 6;
    const int h0  = q * 16;

    float l[16];
#pragma unroll
    for (int hh = 0; hh < 16; hh++) {
        const int h = h0 + hh;
        const float gw = d_G[((size_t)((b * NH + w) * NW + h)) * NIC + i];
        const float gc = d_G[((size_t)((b * NH + h) * NW + w)) * NIC + i];
        l[hh] = gw * gc;
    }
    float m = l[0];
#pragma unroll
    for (int hh = 1; hh < 16; hh++) m = fmaxf(m, l[hh]);
    red[q][i] = m;
    __syncthreads();
    const float M = fmaxf(fmaxf(red[0][i], red[1][i]), fmaxf(red[2][i], red[3][i]));
    __syncthreads();

    float s = 0.0f;
#pragma unroll
    for (int hh = 0; hh < 16; hh++) {
        const float e = __expf(l[hh] - M);
        l[hh] = e;
        s += e;
    }
    red[q][i] = s;
    __syncthreads();
    const float S    = red[0][i] + red[1][i] + red[2][i] + red[3][i];
    const float rinv = 1.0f / S;

#pragma unroll
    for (int hh = 0; hh < 16; hh++) {
        const int h = h0 + hh;
        const size_t o = ((size_t)((b * NH + h) * NW + w)) * NIC + i;
        const float v = l[hh] * rinv * d_Hs[o];
        __nv_bfloat16 ph, pl; hilo(v, ph, pl);
        d_Phi[o] = ph;
        d_Plo[o] = pl;
    }
}

// ---------------------------------------------------------------------------
// K3 v4: 512 threads (2 M-warps x 8 N-warps), B-resident, 4 tiles/CTA,
// cp.async double-buffered A (P hi/lo) AND smem-staged x residual tile
// (issued at mma-start, waited after LN -> x DRAM latency hidden by mma).
// smem: Abuf0 0 | Abuf1 11264 | BH 22528 | BL 89088 | x 155648 (32x520 f32)
//       | red 222208 (32x8x2) | gbuf 224256 (1024 f32)  -> 228352 bytes
// ---------------------------------------------------------------------------
#define K3_SMEM 228352
#define A3_STR 88
#define B3_STR 520
#define X_STR  520

__global__ __launch_bounds__(512, 1)
void k3_mma(const float* __restrict__ gamma, const float* __restrict__ beta,
            const float* __restrict__ scale,
            const float* __restrict__ x, float* __restrict__ out)
{
    extern __shared__ char sm[];
    const uint32_t su = smem_u32(sm);
    const int ABUF = 11264;
    const int BH = 22528, BL = 89088, XS = 155648;
    float (*red)[8][2] = reinterpret_cast<float (*)[8][2]>(sm + 222208);
    float* gbuf        = reinterpret_cast<float*>(sm + 224256);
    float* xsf         = reinterpret_cast<float*>(sm + XS);

    const int tid  = threadIdx.x;
    const int wid  = tid >> 5;
    const int lane = tid & 31;
    const int wn   = wid & 7;                // N warp-block (64 cols)
    const int wm2  = wid >> 3;               // M warp-block (16 rows)
    const float sc = scale[0];

    const int am = tid >> 4;                 // A-load row 0..31
    const int ak = (tid & 15) * 4;           // A-load k 0..60

    if (tid < 128) {
        *reinterpret_cast<float4*>(gbuf + tid * 4) =
            *reinterpret_cast<const float4*>(gamma + tid * 4);
        *reinterpret_cast<float4*>(gbuf + 512 + tid * 4) =
            *reinterpret_cast<const float4*>(beta + tid * 4);
    }
    // B (one-time) + A tile 0, single group
#pragma unroll
    for (int it = 0; it < 8; it++) {
        const int f  = tid + it * 512;
        const int k  = f >> 6;
        const int n8 = (f & 63) * 8;
        cp_a16(su + BH + (k * B3_STR + n8) * 2, d_FH + k * NC + n8);
        cp_a16(su + BL + (k * B3_STR + n8) * 2, d_FL + k * NC + n8);
    }
    {
        const int r0 = blockIdx.x * 4 * 32;
        const size_t go = (size_t)(r0 + am) * NIC + ak;
        cp_a8(su + (am * A3_STR + ak) * 2, d_Phi + go);
        cp_a8(su + 5632 + (am * A3_STR + ak) * 2, d_Plo + go);
    }
    CP_COMMIT();

    for (int t = 0; t < 4; t++) {
        const int row0 = (blockIdx.x * 4 + t) * 32;

        CP_WAIT(0);          // A(t) (and B at t=0) complete
        __syncthreads();     // visible to all; epilogue(t-1) done -> x buf free

        // ---- issue x(t) into smem (hidden under mma below) ----
#pragma unroll
        for (int it = 0; it < 8; it++) {
            const int f  = tid + it * 512;   // 0..4095 float4
            const int r  = f >> 7;           // 0..31
            const int c4 = (f & 127) * 4;    // 0..508
            cp_a16(su + XS + (r * X_STR + c4) * 4,
                   x + (size_t)(row0 + r) * NC + c4);
        }
        CP_COMMIT();                          // group Gx

        if (t < 3) {                          // prefetch A(t+1), other buffer
            const int nb = ((t + 1) & 1) * ABUF;
            const size_t go = (size_t)(row0 + 32 + am) * NIC + ak;
            cp_a8(su + nb + (am * A3_STR + ak) * 2, d_Phi + go);
            cp_a8(su + nb + 5632 + (am * A3_STR + ak) * 2, d_Plo + go);
            CP_COMMIT();                      // group Ga
        }

        const int AHo = (t & 1) * ABUF;
        const int ALo = AHo + 5632;

        float acc[8][4];
#pragma unroll
        for (int ni = 0; ni < 8; ni++)
#pragma unroll
            for (int q = 0; q < 4; q++) acc[ni][q] = 0.0f;

#pragma unroll
        for (int ks = 0; ks < 64; ks += 16) {
            uint32_t ah[4], al_[4];
            {
                const uint32_t off =
                    ((wm2 * 16 + (lane & 15)) * A3_STR + ks + (lane >> 4) * 8) * 2;
                ldsm4(ah,  su + AHo + off);
                ldsm4(al_, su + ALo + off);
            }
            uint32_t bh[4][4], bl[4][4];
#pragma unroll
            for (int p = 0; p < 4; p++) {
                const uint32_t off =
                    ((ks + (lane & 15)) * B3_STR + wn * 64 + p * 16 + (lane >> 4) * 8) * 2;
                ldsm4t(bh[p], su + BH + off);
                ldsm4t(bl[p], su + BL + off);
            }
#pragma unroll
            for (int p = 0; p < 4; p++)
#pragma unroll
                for (int ns = 0; ns < 2; ns++) {
                    const int ni = p * 2 + ns;
                    mma16816(acc[ni], ah,  bh[p][2 * ns], bh[p][2 * ns + 1]);
                    mma16816(acc[ni], ah,  bl[p][2 * ns], bl[p][2 * ns + 1]);
                    mma16816(acc[ni], al_, bh[p][2 * ns], bh[p][2 * ns + 1]);
                }
        }

        // ---- LN reduction (quad shfl + 8-warp combine via red) ----
#pragma unroll
        for (int half = 0; half < 2; half++) {
            float s = 0.f, ss = 0.f;
#pragma unroll
            for (int ni = 0; ni < 8; ni++) {
                const float v0 = acc[ni][half * 2];
                const float v1 = acc[ni][half * 2 + 1];
                s += v0 + v1; ss += v0 * v0 + v1 * v1;
            }
#pragma unroll
            for (int o = 1; o < 4; o <<= 1) {
                s  += __shfl_xor_sync(0xffffffffu, s,  o);
                ss += __shfl_xor_sync(0xffffffffu, ss, o);
            }
            if ((lane & 3) == 0) {
                const int r = wm2 * 16 + (lane >> 2) + half * 8;
                red[r][wn][0] = s;
                red[r][wn][1] = ss;
            }
        }

        // x(t) arrived long ago (hidden under mma); Ga may still fly (t<3)
        if (t < 3) { CP_WAIT(1); } else { CP_WAIT(0); }
        __syncthreads();     // red + x visible

        float mean[2], inv[2];
#pragma unroll
        for (int half = 0; half < 2; half++) {
            const int r = wm2 * 16 + (lane >> 2) + half * 8;
            float S = 0.f, SS = 0.f;
#pragma unroll
            for (int w8 = 0; w8 < 8; w8++) { S += red[r][w8][0]; SS += red[r][w8][1]; }
            const float m = S * (1.0f / NC);
            mean[half] = m;
            inv[half]  = rsqrtf(SS * (1.0f / NC) - m * m + LN_EPS);
        }

        // ---- apply + residual (x from smem), write out ----
#pragma unroll
        for (int ni = 0; ni < 8; ni++) {
            const int col = wn * 64 + ni * 8 + (lane & 3) * 2;
            const float g0 = gbuf[col],       g1 = gbuf[col + 1];
            const float b0 = gbuf[512 + col], b1 = gbuf[512 + col + 1];
#pragma unroll
            for (int half = 0; half < 2; half++) {
                const int rl = wm2 * 16 + (lane >> 2) + half * 8;
                const float2 x2 = *reinterpret_cast<const float2*>(
                    xsf + rl * X_STR + col);
                float2 o;
                o.x = x2.x + ((acc[ni][half * 2]     - mean[half]) * inv[half] * g0 + b0) * sc;
                o.y = x2.y + ((acc[ni][half * 2 + 1] - mean[half]) * inv[half] * g1 + b1) * sc;
                *reinterpret_cast<float2*>(out + (size_t)(row0 + rl) * NC + col) = o;
            }
        }
    }
}

// ---------------------------------------------------------------------------
// Launch. Inputs: 0:x 1:w_f 2:w_h 3:w_fgh 4:gamma_f 5:beta_f 6:gamma_h
// 7:beta_h 8:gamma_fgh 9:beta_fgh 10:scale
// ---------------------------------------------------------------------------
extern "C" void kernel_launch(void* const* d_in, const int* in_sizes, int n_in,
                              void* d_out, int out_size)
{
    (void)in_sizes; (void)n_in; (void)out_size;
    const float* x         = (const float*)d_in[0];
    const float* w_f       = (const float*)d_in[1];
    const float* w_h       = (const float*)d_in[2];
    const float* w_fgh     = (const float*)d_in[3];
    const float* gamma_f   = (const float*)d_in[4];
    const float* beta_f    = (const float*)d_in[5];
    const float* gamma_h   = (const float*)d_in[6];
    const float* beta_h    = (const float*)d_in[7];
    const float* gamma_fgh = (const float*)d_in[8];
    const float* beta_fgh  = (const float*)d_in[9];
    const float* scale     = (const float*)d_in[10];
    float* out             = (float*)d_out;

    cudaFuncSetAttribute(k1_mma, cudaFuncAttributeMaxDynamicSharedMemorySize, K1_SMEM);
    cudaFuncSetAttribute(k3_mma, cudaFuncAttributeMaxDynamicSharedMemorySize, K3_SMEM);

    k0_prep<<<384, 256>>>(w_f, w_h, w_fgh);
    k1_mma<<<NROWS / 128, 512, K1_SMEM>>>(x, gamma_f, beta_f, gamma_h, beta_h);
    k2_softmax<<<NB * NW, 256>>>();
    k3_mma<<<NROWS / 128, 512, K3_SMEM>>>(gamma_fgh, beta_fgh, scale, x, out);
}